// round 6
// baseline (speedup 1.0000x reference)
#include <cuda_runtime.h>
#include <cuda_bf16.h>
#include <cstdint>
#include <cstddef>

// Problem constants
#define BB 2
#define TT 2048
#define DD 768
#define HH 12
#define HS 64
#define FF 3072
#define HALF 1536
#define NT (BB*TT)       // 4096
#define QKVN 2304        // fused q|k|v output width
#define BH 24            // B*H
#define SCL 0.03608439182435161f   // 768^-0.5

// ---------------- scratch (device globals) -----------------------------------
__device__ float g_qkv[(size_t)NT*QKVN];
__device__ float g_x1 [(size_t)NT*DD];
// activation splits: hi block then lo block
__device__ __nv_bfloat16 g_ah [(size_t)2*NT*DD];    // rmsnorm1 out
__device__ __nv_bfloat16 g_atb[(size_t)2*NT*DD];    // attention out
__device__ __nv_bfloat16 g_h2b[(size_t)2*NT*DD];    // rmsnorm2 out
__device__ __nv_bfloat16 g_swb[(size_t)2*NT*HALF];  // swiglu out (from W1 epi)
// per-head K/V splits: K [bh][t][64] hi|lo ; V transposed [bh][c][T] hi|lo
__device__ __nv_bfloat16 g_kb [(size_t)2*BH*TT*HS];
__device__ __nv_bfloat16 g_vb [(size_t)2*BH*TT*HS];
// weight splits: hi block [N*K] then lo block [N*K], layout [N][K]
__device__ __nv_bfloat16 g_bqkv[(size_t)2*QKVN*DD];
__device__ __nv_bfloat16 g_bo  [(size_t)2*DD*DD];
__device__ __nv_bfloat16 g_b1  [(size_t)2*FF*DD];   // column-interleaved (val,gate)
__device__ __nv_bfloat16 g_b2  [(size_t)2*DD*HALF];

// ---------------- helpers ----------------------------------------------------
__device__ __forceinline__ uint32_t smem_u32(const void* p) {
    uint32_t a;
    asm("{ .reg .u64 t; cvta.to.shared.u64 t, %1; cvt.u32.u64 %0, t; }" : "=r"(a) : "l"(p));
    return a;
}
#define CPASYNC(d, s) asm volatile("cp.async.cg.shared.global [%0], [%1], 16;" :: "r"(d), "l"(s) : "memory")
#define CPCOMMIT()    asm volatile("cp.async.commit_group;" ::: "memory")
#define CPWAIT(n)     asm volatile("cp.async.wait_group %0;" :: "n"(n) : "memory")
#define LDSM4(r, a)                                                              \
    asm volatile("ldmatrix.sync.aligned.m8n8.x4.shared.b16 {%0,%1,%2,%3}, [%4];" \
        : "=r"((r)[0]), "=r"((r)[1]), "=r"((r)[2]), "=r"((r)[3]) : "r"(a))
#define MMA16816(c, a, b0, b1)                                                   \
    asm volatile("mma.sync.aligned.m16n8k16.row.col.f32.bf16.bf16.f32 "          \
        "{%0,%1,%2,%3}, {%4,%5,%6,%7}, {%8,%9}, {%0,%1,%2,%3};"                  \
        : "+f"((c)[0]), "+f"((c)[1]), "+f"((c)[2]), "+f"((c)[3])                 \
        : "r"((a)[0]), "r"((a)[1]), "r"((a)[2]), "r"((a)[3]), "r"(b0), "r"(b1))

__device__ __forceinline__ void split2(float v, __nv_bfloat16& h, __nv_bfloat16& l) {
    h = __float2bfloat16_rn(v);
    l = __float2bfloat16_rn(v - __bfloat162float(h));
}
__device__ __forceinline__ uint32_t packbf(__nv_bfloat16 lo, __nv_bfloat16 hi) {
    return (uint32_t)__bfloat16_as_ushort(lo) | ((uint32_t)__bfloat16_as_ushort(hi) << 16);
}

// ---------------- fused weight prep (single launch) ---------------------------
// transpose/split all 6 weight matrices into [N][K] bf16 hi/lo.
// W1 is additionally column-interleaved: out row n' <- src col (n'&1 ? 1536+n'/2 : n'/2)
#define CQ (768*192)
#define CO (768*192)
#define C1 (3072*192)
#define C2 (768*384)

__global__ void __launch_bounds__(256) prep_all(
    const float* __restrict__ Wq, const float* __restrict__ Wk,
    const float* __restrict__ Wv, const float* __restrict__ Wo,
    const float* __restrict__ W1, const float* __restrict__ W2,
    __nv_bfloat16* __restrict__ bqkv, __nv_bfloat16* __restrict__ bo,
    __nv_bfloat16* __restrict__ b1,  __nv_bfloat16* __restrict__ b2)
{
    int idx = blockIdx.x * 256 + threadIdx.x;
    const float* W; __nv_bfloat16 *hi, *lo;
    int N, K, mode, srcLd, local;
    if (idx < 3 * CQ) {
        int m = idx / CQ; local = idx - m * CQ;
        W = (m == 0) ? Wq : (m == 1) ? Wk : Wv;
        hi = bqkv + (size_t)m * 768 * 768;
        lo = bqkv + (size_t)QKVN * DD + (size_t)m * 768 * 768;
        N = 768; K = 768; mode = 1; srcLd = 0;
    } else if (idx < 3 * CQ + CO) {
        local = idx - 3 * CQ; W = Wo;
        hi = bo; lo = bo + (size_t)768 * 768;
        N = 768; K = 768; mode = 0; srcLd = 768;
    } else if (idx < 3 * CQ + CO + C1) {
        local = idx - 3 * CQ - CO; W = W1;
        hi = b1; lo = b1 + (size_t)3072 * 768;
        N = 3072; K = 768; mode = 2; srcLd = 3072;
    } else {
        local = idx - 3 * CQ - CO - C1; W = W2;
        hi = b2; lo = b2 + (size_t)768 * 1536;
        N = 768; K = 1536; mode = 0; srcLd = 768;
    }
    int kq = K >> 2;
    int n = local / kq, k = (local - n * kq) << 2;
    int srcn = (mode == 2) ? (((n & 1) ? HALF : 0) + (n >> 1)) : n;
    union { __nv_bfloat16 b[4]; uint2 u; } H, L;
    #pragma unroll
    for (int j = 0; j < 4; j++) {
        size_t sa = (mode == 1)
            ? (size_t)(n >> 6) * ((size_t)K * 64) + (size_t)(k + j) * 64 + (n & 63)
            : (size_t)(k + j) * srcLd + srcn;
        split2(W[sa], H.b[j], L.b[j]);
    }
    *(uint2*)(hi + (size_t)n * K + k) = H.u;
    *(uint2*)(lo + (size_t)n * K + k) = L.u;
}
#define PREP_GRID ((3*CQ + CO + C1 + C2) / 256)   // 5760

// ---------------- mma.sync bf16-split GEMM -----------------------------------
// CTA 128x128, warp 64x32, K-block 32, 2-stage cp.async, fragment-reuse loop.
// emode 0: C = acc + bias + resid (fp32)
// emode 1: swiglu — acc cols are interleaved (val,gate) pairs; writes
//          silu(gate+bias_g)*(val+bias_v) as bf16 hi/lo split into Csp [M][HALF].
#define KB 32
#define PADE 40
#define TILEB (128*PADE*2)
#define STGB  (4*TILEB)
#define GEMM_SMEM (2*STGB)

__global__ void __launch_bounds__(256, 2) gemm_mma(
    const __nv_bfloat16* __restrict__ Ap, const __nv_bfloat16* __restrict__ Bp,
    const float* __restrict__ bias, const float* __restrict__ resid,
    float* __restrict__ C, __nv_bfloat16* __restrict__ Csp,
    int M, int N, int K, int emode)
{
    extern __shared__ char sm[];
    const size_t MK = (size_t)M * K, NK = (size_t)N * K;
    int tid = threadIdx.x, lane = tid & 31, wid = tid >> 5;
    int wm = wid >> 2, wn = wid & 3;
    int bm = blockIdx.y * 128, bn = blockIdx.x * 128;
    uint32_t sbase = smem_u32(sm);

    float acc[4][4][4];
    #pragma unroll
    for (int i = 0; i < 4; i++)
        #pragma unroll
        for (int j = 0; j < 4; j++)
            #pragma unroll
            for (int q = 0; q < 4; q++) acc[i][j][q] = 0.f;

    int a_r = lane & 15, a_c = (lane & 16) ? 8 : 0;
    int b_r = ((lane >> 4) << 3) + (lane & 7), b_c = (lane & 8);
    const int KBn = K / KB;

    auto load_stage = [&](int kb, int stg) {
        #pragma unroll
        for (int t4 = 0; t4 < 4; t4++) {
            const __nv_bfloat16* base =
                (t4 < 2) ? (Ap + (t4 ? MK : 0)) : (Bp + (t4 == 3 ? NK : 0));
            int rowbase = (t4 < 2) ? bm : bn;
            #pragma unroll
            for (int i = 0; i < 2; i++) {
                int c = i * 256 + tid;
                int row = c >> 2, cc = c & 3;
                uint32_t dst = sbase + stg * STGB + t4 * TILEB
                             + (uint32_t)(row * (PADE * 2) + cc * 16);
                const __nv_bfloat16* src =
                    base + (size_t)(rowbase + row) * K + kb * KB + cc * 8;
                CPASYNC(dst, src);
            }
        }
    };

    load_stage(0, 0);
    CPCOMMIT();

    for (int kb = 0; kb < KBn; kb++) {
        if (kb + 1 < KBn) {
            load_stage(kb + 1, (kb + 1) & 1);
            CPCOMMIT();
            CPWAIT(1);
        } else {
            CPWAIT(0);
        }
        __syncthreads();

        uint32_t sa = sbase + (kb & 1) * STGB;
        uint32_t aoh = sa, aol = sa + TILEB, boh = sa + 2 * TILEB, bol = sa + 3 * TILEB;
        #pragma unroll
        for (int ks = 0; ks < KB; ks += 16) {
            uint32_t ah[4][4], al[4][4], bf2[2][4];
            #pragma unroll
            for (int mt = 0; mt < 4; mt++) {
                uint32_t off = (uint32_t)(((wm * 64 + mt * 16 + a_r) * PADE + ks + a_c) * 2);
                LDSM4(ah[mt], aoh + off);
                LDSM4(al[mt], aol + off);
            }
            #pragma unroll
            for (int np = 0; np < 2; np++) {
                uint32_t off = (uint32_t)(((wn * 32 + np * 16 + b_r) * PADE + ks + b_c) * 2);
                LDSM4(bf2[np], boh + off);
            }
            #pragma unroll
            for (int mt = 0; mt < 4; mt++)
                #pragma unroll
                for (int nt = 0; nt < 4; nt++)
                    MMA16816(acc[mt][nt], ah[mt],
                             bf2[nt >> 1][(nt & 1) * 2], bf2[nt >> 1][(nt & 1) * 2 + 1]);
            #pragma unroll
            for (int mt = 0; mt < 4; mt++)
                #pragma unroll
                for (int nt = 0; nt < 4; nt++)
                    MMA16816(acc[mt][nt], al[mt],
                             bf2[nt >> 1][(nt & 1) * 2], bf2[nt >> 1][(nt & 1) * 2 + 1]);
            #pragma unroll
            for (int np = 0; np < 2; np++) {
                uint32_t off = (uint32_t)(((wn * 32 + np * 16 + b_r) * PADE + ks + b_c) * 2);
                LDSM4(bf2[np], bol + off);
            }
            #pragma unroll
            for (int mt = 0; mt < 4; mt++)
                #pragma unroll
                for (int nt = 0; nt < 4; nt++)
                    MMA16816(acc[mt][nt], ah[mt],
                             bf2[nt >> 1][(nt & 1) * 2], bf2[nt >> 1][(nt & 1) * 2 + 1]);
        }
        __syncthreads();
    }

    int g = lane >> 2, t = lane & 3;
    if (emode == 0) {
        #pragma unroll
        for (int mt = 0; mt < 4; mt++) {
            #pragma unroll
            for (int half = 0; half < 2; half++) {
                int row = bm + wm * 64 + mt * 16 + g + half * 8;
                float* cp = C + (size_t)row * N;
                const float* rp = resid ? (resid + (size_t)row * N) : nullptr;
                #pragma unroll
                for (int nt = 0; nt < 4; nt++) {
                    int col = bn + wn * 32 + nt * 8 + t * 2;
                    float2 v;
                    v.x = acc[mt][nt][half * 2 + 0];
                    v.y = acc[mt][nt][half * 2 + 1];
                    if (bias) {
                        float2 b2v = *(const float2*)(bias + col);
                        v.x += b2v.x; v.y += b2v.y;
                    }
                    if (rp) {
                        float2 r2v = *(const float2*)(rp + col);
                        v.x += r2v.x; v.y += r2v.y;
                    }
                    *(float2*)(cp + col) = v;
                }
            }
        }
    } else {
        // swiglu epilogue: acc pair (even=value, odd=gate) -> bf16 hi/lo split
        const size_t LOS = (size_t)M * HALF;
        #pragma unroll
        for (int mt = 0; mt < 4; mt++) {
            #pragma unroll
            for (int half = 0; half < 2; half++) {
                int row = bm + wm * 64 + mt * 16 + g + half * 8;
                #pragma unroll
                for (int nt = 0; nt < 4; nt++) {
                    int gcol = bn + wn * 32 + nt * 8 + t * 2;  // even
                    int j = gcol >> 1;
                    float val = acc[mt][nt][half * 2 + 0] + bias[j];
                    float gt  = acc[mt][nt][half * 2 + 1] + bias[HALF + j];
                    float s = gt / (1.0f + __expf(-gt));
                    float r = s * val;
                    __nv_bfloat16 h, l; split2(r, h, l);
                    Csp[(size_t)row * HALF + j] = h;
                    Csp[LOS + (size_t)row * HALF + j] = l;
                }
            }
        }
    }
}

// ---------------- split K/V into per-head bf16 hi/lo layouts ------------------
__global__ void __launch_bounds__(256) split_kv(
    const float* __restrict__ QKV, __nv_bfloat16* __restrict__ KBo,
    __nv_bfloat16* __restrict__ VBo)
{
    __shared__ float vs[64][65];
    int tid = threadIdx.x;
    int tt = blockIdx.x, bh = blockIdx.y;
    int b = bh / HH, hh = bh % HH;
    const size_t LO = (size_t)BH * TT * HS;

    #pragma unroll
    for (int i = 0; i < 8; i++) {
        int p = i * 256 + tid;
        int row = p >> 5, c = (p & 31) * 2;
        const float* s = QKV + (size_t)(b * TT + tt * 64 + row) * QKVN + DD + hh * HS + c;
        __nv_bfloat16 h0, l0, h1, l1;
        split2(s[0], h0, l0); split2(s[1], h1, l1);
        size_t o = ((size_t)bh * TT + tt * 64 + row) * HS + c;
        *(uint32_t*)(KBo + o)      = packbf(h0, h1);
        *(uint32_t*)(KBo + LO + o) = packbf(l0, l1);
    }
    #pragma unroll
    for (int i = 0; i < 8; i++) {
        int p = i * 256 + tid;
        int row = p >> 5, c = (p & 31) * 2;
        const float* s = QKV + (size_t)(b * TT + tt * 64 + row) * QKVN + 2 * DD + hh * HS + c;
        vs[row][c] = s[0]; vs[row][c + 1] = s[1];
    }
    __syncthreads();
    #pragma unroll
    for (int i = 0; i < 8; i++) {
        int p = i * 256 + tid;
        int c = p >> 5, t2 = (p & 31) * 2;
        __nv_bfloat16 h0, l0, h1, l1;
        split2(vs[t2][c], h0, l0); split2(vs[t2 + 1][c], h1, l1);
        size_t o = ((size_t)bh * HS + c) * TT + tt * 64 + t2;
        *(uint32_t*)(VBo + o)      = packbf(h0, h1);
        *(uint32_t*)(VBo + LO + o) = packbf(l0, l1);
    }
}

// ---------------- tensor-core causal flash attention --------------------------
#define ATT_STG 36864
#define ATT_SMEM (36864 + 2*ATT_STG)

__global__ void __launch_bounds__(256, 2) attn_tc(
    const float* __restrict__ QKV, const __nv_bfloat16* __restrict__ KBi,
    const __nv_bfloat16* __restrict__ VBi, __nv_bfloat16* __restrict__ ATB)
{
    extern __shared__ char sm[];
    uint32_t sbase = smem_u32(sm);
    int tid = threadIdx.x, lane = tid & 31, wid = tid >> 5;
    int qt = (int)(gridDim.x - 1 - blockIdx.x);
    int bh = blockIdx.y, b = bh / HH, hh = bh % HH;
    int q0 = qt * 128;
    const size_t LO = (size_t)BH * TT * HS;
    int nkt = 2 * qt + 2;

    int a_r = lane & 15, a_c = (lane & 16) ? 8 : 0;
    int b_r = ((lane >> 4) << 3) + (lane & 7), b_c = lane & 8;
    int g = lane >> 2, tq = lane & 3;

    auto ldkv = [&](int kt, int stg) {
        uint32_t sb2 = sbase + 36864 + stg * ATT_STG;
        size_t kbase = ((size_t)bh * TT + kt * 64) * HS;
        size_t vbase = (size_t)bh * HS * TT + kt * 64;
        #pragma unroll
        for (int i = 0; i < 8; i++) {
            int ch = i * 256 + tid;
            int tile = ch >> 9;
            int r = (ch >> 3) & 63, cc = ch & 7;
            uint32_t dst = sb2 + tile * 9216 + r * 144 + cc * 16;
            const __nv_bfloat16* src;
            if (tile == 0)      src = KBi + kbase + r * 64 + cc * 8;
            else if (tile == 1) src = KBi + LO + kbase + r * 64 + cc * 8;
            else if (tile == 2) src = VBi + vbase + (size_t)r * TT + cc * 8;
            else                src = VBi + LO + vbase + (size_t)r * TT + cc * 8;
            CPASYNC(dst, src);
        }
    };

    ldkv(0, 0);
    CPCOMMIT();

    for (int p = tid; p < 4096; p += 256) {
        int row = p >> 5, c = (p & 31) * 2;
        const float* s = QKV + (size_t)(b * TT + q0 + row) * QKVN + hh * HS + c;
        __nv_bfloat16 h0, l0, h1, l1;
        split2(s[0] * SCL, h0, l0); split2(s[1] * SCL, h1, l1);
        *(uint32_t*)(sm + (row * 72 + c) * 2)         = packbf(h0, h1);
        *(uint32_t*)(sm + 18432 + (row * 72 + c) * 2) = packbf(l0, l1);
    }
    __syncthreads();

    float oacc[8][4];
    #pragma unroll
    for (int n = 0; n < 8; n++)
        #pragma unroll
        for (int j = 0; j < 4; j++) oacc[n][j] = 0.f;
    float lsum0 = 0.f, lsum1 = 0.f;

    for (int kt = 0; kt < nkt; kt++) {
        if (kt + 1 < nkt) { ldkv(kt + 1, (kt + 1) & 1); CPCOMMIT(); CPWAIT(1); }
        else              { CPWAIT(0); }
        __syncthreads();

        uint32_t KHb = sbase + 36864 + (kt & 1) * ATT_STG;
        uint32_t KLb = KHb + 9216, VHb = KHb + 18432, VLb = KHb + 27648;

        float sacc[8][4];
        #pragma unroll
        for (int n = 0; n < 8; n++)
            #pragma unroll
            for (int j = 0; j < 4; j++) sacc[n][j] = 0.f;

        #pragma unroll
        for (int ks = 0; ks < 4; ks++) {
            uint32_t qh[4], ql[4];
            uint32_t qa = sbase + (uint32_t)(((wid * 16 + a_r) * 72 + ks * 16 + a_c) * 2);
            LDSM4(qh, qa);
            LDSM4(ql, qa + 18432);
            #pragma unroll
            for (int nt2 = 0; nt2 < 4; nt2++) {
                uint32_t kf[4];
                uint32_t ka = (uint32_t)(((nt2 * 16 + b_r) * 72 + ks * 16 + b_c) * 2);
                LDSM4(kf, KHb + ka);
                MMA16816(sacc[2*nt2],     qh, kf[0], kf[1]);
                MMA16816(sacc[2*nt2 + 1], qh, kf[2], kf[3]);
                MMA16816(sacc[2*nt2],     ql, kf[0], kf[1]);
                MMA16816(sacc[2*nt2 + 1], ql, kf[2], kf[3]);
                LDSM4(kf, KLb + ka);
                MMA16816(sacc[2*nt2],     qh, kf[0], kf[1]);
                MMA16816(sacc[2*nt2 + 1], qh, kf[2], kf[3]);
            }
        }

        bool msk = (kt >= 2 * qt);
        int r0 = q0 + wid * 16 + g, r1 = r0 + 8;
        int cb = kt * 64 + tq * 2;
        #pragma unroll
        for (int n = 0; n < 8; n++) {
            #pragma unroll
            for (int j = 0; j < 4; j++) {
                int c = cb + n * 8 + (j & 1);
                int r = (j < 2) ? r0 : r1;
                sacc[n][j] = (!msk || c <= r) ? __expf(sacc[n][j]) : 0.f;
            }
        }

        #pragma unroll
        for (int pk = 0; pk < 4; pk++) {
            __nv_bfloat16 p00 = __float2bfloat16_rn(sacc[2*pk][0]);
            __nv_bfloat16 p01 = __float2bfloat16_rn(sacc[2*pk][1]);
            __nv_bfloat16 p02 = __float2bfloat16_rn(sacc[2*pk][2]);
            __nv_bfloat16 p03 = __float2bfloat16_rn(sacc[2*pk][3]);
            __nv_bfloat16 p10 = __float2bfloat16_rn(sacc[2*pk+1][0]);
            __nv_bfloat16 p11 = __float2bfloat16_rn(sacc[2*pk+1][1]);
            __nv_bfloat16 p12 = __float2bfloat16_rn(sacc[2*pk+1][2]);
            __nv_bfloat16 p13 = __float2bfloat16_rn(sacc[2*pk+1][3]);
            lsum0 += __bfloat162float(p00) + __bfloat162float(p01)
                   + __bfloat162float(p10) + __bfloat162float(p11);
            lsum1 += __bfloat162float(p02) + __bfloat162float(p03)
                   + __bfloat162float(p12) + __bfloat162float(p13);
            uint32_t pa[4];
            pa[0] = packbf(p00, p01);
            pa[1] = packbf(p02, p03);
            pa[2] = packbf(p10, p11);
            pa[3] = packbf(p12, p13);
            #pragma unroll
            for (int nt2 = 0; nt2 < 4; nt2++) {
                uint32_t vf[4];
                uint32_t va = (uint32_t)(((nt2 * 16 + b_r) * 72 + pk * 16 + b_c) * 2);
                LDSM4(vf, VHb + va);
                MMA16816(oacc[2*nt2],     pa, vf[0], vf[1]);
                MMA16816(oacc[2*nt2 + 1], pa, vf[2], vf[3]);
                LDSM4(vf, VLb + va);
                MMA16816(oacc[2*nt2],     pa, vf[0], vf[1]);
                MMA16816(oacc[2*nt2 + 1], pa, vf[2], vf[3]);
            }
        }
        __syncthreads();
    }

    lsum0 += __shfl_xor_sync(0xffffffffu, lsum0, 1);
    lsum0 += __shfl_xor_sync(0xffffffffu, lsum0, 2);
    lsum1 += __shfl_xor_sync(0xffffffffu, lsum1, 1);
    lsum1 += __shfl_xor_sync(0xffffffffu, lsum1, 2);
    float inv0 = 1.0f / lsum0, inv1 = 1.0f / lsum1;

    const size_t LOA = (size_t)NT * DD;
    size_t rg0 = (size_t)(b * TT + q0 + wid * 16 + g);
    size_t rg1 = rg0 + 8;
    int lc = hh * HS + tq * 2;
    #pragma unroll
    for (int n = 0; n < 8; n++) {
        __nv_bfloat16 h0, l0, h1, l1;
        split2(oacc[n][0] * inv0, h0, l0);
        split2(oacc[n][1] * inv0, h1, l1);
        *(uint32_t*)(ATB + rg0 * DD + lc + n * 8)       = packbf(h0, h1);
        *(uint32_t*)(ATB + LOA + rg0 * DD + lc + n * 8) = packbf(l0, l1);
        split2(oacc[n][2] * inv1, h0, l0);
        split2(oacc[n][3] * inv1, h1, l1);
        *(uint32_t*)(ATB + rg1 * DD + lc + n * 8)       = packbf(h0, h1);
        *(uint32_t*)(ATB + LOA + rg1 * DD + lc + n * 8) = packbf(l0, l1);
    }
}

// ---------------- RMSNorm -> bf16 hi/lo --------------------------------------
__global__ void __launch_bounds__(256) rmsnorm_split(
    const float* __restrict__ x, const float* __restrict__ gw,
    __nv_bfloat16* __restrict__ o)
{
    int row = blockIdx.x;
    const float* xr = x + (size_t)row * DD;
    int tid = threadIdx.x;
    float ss = 0.f;
    for (int i = tid; i < DD; i += 256) { float v = xr[i]; ss += v * v; }
    #pragma unroll
    for (int o2 = 16; o2 > 0; o2 >>= 1) ss += __shfl_xor_sync(0xffffffffu, ss, o2);
    __shared__ float red[8];
    if ((tid & 31) == 0) red[tid >> 5] = ss;
    __syncthreads();
    if (tid < 8) {
        float v = red[tid];
        #pragma unroll
        for (int o2 = 4; o2 > 0; o2 >>= 1) v += __shfl_xor_sync(0xffu, v, o2);
        if (tid == 0) red[0] = v;
    }
    __syncthreads();
    float rms = sqrtf(red[0] * (1.0f / DD));
    float inv = 1.0f / (rms + 1e-8f);
    const size_t LOA = (size_t)NT * DD;
    for (int i = tid; i < DD; i += 256) {
        float v = gw[i] * xr[i] * inv;
        __nv_bfloat16 h, l; split2(v, h, l);
        o[(size_t)row * DD + i] = h;
        o[LOA + (size_t)row * DD + i] = l;
    }
}

// ---------------- launch -----------------------------------------------------
extern "C" void kernel_launch(void* const* d_in, const int* in_sizes, int n_in,
                              void* d_out, int out_size)
{
    const float* x  = (const float*)d_in[0];
    const float* Wq = (const float*)d_in[1];
    const float* Wk = (const float*)d_in[2];
    const float* Wv = (const float*)d_in[3];
    const float* Wo = (const float*)d_in[4];
    const float* bo = (const float*)d_in[5];
    const float* W1 = (const float*)d_in[6];
    const float* b1 = (const float*)d_in[7];
    const float* W2 = (const float*)d_in[8];
    const float* b2 = (const float*)d_in[9];
    const float* g1 = (const float*)d_in[10];
    const float* g2 = (const float*)d_in[11];
    float* out = (float*)d_out;

    float *qkv, *x1;
    __nv_bfloat16 *ah, *atb, *h2b, *swb, *kb, *vb, *bqkv, *bo_, *b1_, *b2_;
    cudaGetSymbolAddress((void**)&qkv, g_qkv);
    cudaGetSymbolAddress((void**)&x1,  g_x1);
    cudaGetSymbolAddress((void**)&ah,  g_ah);
    cudaGetSymbolAddress((void**)&atb, g_atb);
    cudaGetSymbolAddress((void**)&h2b, g_h2b);
    cudaGetSymbolAddress((void**)&swb, g_swb);
    cudaGetSymbolAddress((void**)&kb,  g_kb);
    cudaGetSymbolAddress((void**)&vb,  g_vb);
    cudaGetSymbolAddress((void**)&bqkv, g_bqkv);
    cudaGetSymbolAddress((void**)&bo_,  g_bo);
    cudaGetSymbolAddress((void**)&b1_,  g_b1);
    cudaGetSymbolAddress((void**)&b2_,  g_b2);

    cudaFuncSetAttribute(gemm_mma, cudaFuncAttributeMaxDynamicSharedMemorySize, GEMM_SMEM);
    cudaFuncSetAttribute(attn_tc,  cudaFuncAttributeMaxDynamicSharedMemorySize, ATT_SMEM);

    // 0) all weight prep in one launch
    prep_all<<<PREP_GRID, 256>>>(Wq, Wk, Wv, Wo, W1, W2, bqkv, bo_, b1_, b2_);

    // 1) ah = split(rmsnorm(x, g1))
    rmsnorm_split<<<NT, 256>>>(x, g1, ah);

    // 2) qkv = ah @ [Wq|Wk|Wv]
    gemm_mma<<<dim3(QKVN / 128, NT / 128), 256, GEMM_SMEM>>>(
        ah, bqkv, nullptr, nullptr, qkv, nullptr, NT, QKVN, DD, 0);

    // 3) split K/V into per-head hi/lo layouts
    split_kv<<<dim3(TT / 64, BH), 256>>>(qkv, kb, vb);

    // 4) tensor-core attention -> atb (split)
    attn_tc<<<dim3(TT / 128, BH), 256, ATT_SMEM>>>(qkv, kb, vb, atb);

    // 5) x1 = x + atb @ Wo + bo   (<- ncu sample target)
    gemm_mma<<<dim3(DD / 128, NT / 128), 256, GEMM_SMEM>>>(
        atb, bo_, bo, x, x1, nullptr, NT, DD, DD, 0);

    // 6) h2b = split(rmsnorm(x1, g2))
    rmsnorm_split<<<NT, 256>>>(x1, g2, h2b);

    // 7) swb = swiglu(h2b @ W1' + b1)  — fused epilogue, interleaved W1
    gemm_mma<<<dim3(FF / 128, NT / 128), 256, GEMM_SMEM>>>(
        h2b, b1_, b1, nullptr, nullptr, swb, NT, FF, DD, 1);

    // 8) out = x1 + swb @ W2 + b2
    gemm_mma<<<dim3(DD / 128, NT / 128), 256, GEMM_SMEM>>>(
        swb, b2_, b2, x1, out, nullptr, NT, DD, HALF, 0);
}

// round 7
// speedup vs baseline: 2.1648x; 2.1648x over previous
#include <cuda_runtime.h>
#include <cuda_fp16.h>
#include <cstdint>
#include <cstddef>

// Problem constants
#define BB 2
#define TT 2048
#define DD 768
#define HH 12
#define HS 64
#define FF 3072
#define HALF 1536
#define NT (BB*TT)       // 4096
#define QKVN 2304        // fused q|k|v output width
#define BH 24            // B*H
#define SCL 0.03608439182435161f   // 768^-0.5

// ---------------- scratch (device globals) -----------------------------------
__device__ float g_qkv[(size_t)NT*QKVN];
__device__ float g_x1 [(size_t)NT*DD];
// fp16 activations
__device__ __half g_ah [(size_t)NT*DD];    // rmsnorm1 out
__device__ __half g_atb[(size_t)NT*DD];    // attention out
__device__ __half g_h2b[(size_t)NT*DD];    // rmsnorm2 out
__device__ __half g_swb[(size_t)NT*HALF];  // swiglu out (from W1 epi)
// per-head K/V: K [bh][t][64] ; V transposed [bh][c][T]
__device__ __half g_kb [(size_t)BH*TT*HS];
__device__ __half g_vb [(size_t)BH*TT*HS];
// fp16 weights, layout [N][K]
__device__ __half g_bqkv[(size_t)QKVN*DD];
__device__ __half g_bo  [(size_t)DD*DD];
__device__ __half g_b1  [(size_t)FF*DD];   // column-interleaved (val,gate)
__device__ __half g_b2  [(size_t)DD*HALF];

// ---------------- helpers ----------------------------------------------------
__device__ __forceinline__ uint32_t smem_u32(const void* p) {
    uint32_t a;
    asm("{ .reg .u64 t; cvta.to.shared.u64 t, %1; cvt.u32.u64 %0, t; }" : "=r"(a) : "l"(p));
    return a;
}
#define CPASYNC(d, s) asm volatile("cp.async.cg.shared.global [%0], [%1], 16;" :: "r"(d), "l"(s) : "memory")
#define CPCOMMIT()    asm volatile("cp.async.commit_group;" ::: "memory")
#define CPWAIT(n)     asm volatile("cp.async.wait_group %0;" :: "n"(n) : "memory")
#define LDSM4(r, a)                                                              \
    asm volatile("ldmatrix.sync.aligned.m8n8.x4.shared.b16 {%0,%1,%2,%3}, [%4];" \
        : "=r"((r)[0]), "=r"((r)[1]), "=r"((r)[2]), "=r"((r)[3]) : "r"(a))
#define MMA16816(c, a, b0, b1)                                                   \
    asm volatile("mma.sync.aligned.m16n8k16.row.col.f32.f16.f16.f32 "            \
        "{%0,%1,%2,%3}, {%4,%5,%6,%7}, {%8,%9}, {%0,%1,%2,%3};"                  \
        : "+f"((c)[0]), "+f"((c)[1]), "+f"((c)[2]), "+f"((c)[3])                 \
        : "r"((a)[0]), "r"((a)[1]), "r"((a)[2]), "r"((a)[3]), "r"(b0), "r"(b1))

__device__ __forceinline__ uint32_t packh(__half a, __half b) {
    return (uint32_t)__half_as_ushort(a) | ((uint32_t)__half_as_ushort(b) << 16);
}

// ---------------- fused weight prep (single launch) ---------------------------
#define CQ (768*192)
#define CO (768*192)
#define C1 (3072*192)
#define C2 (768*384)

__global__ void __launch_bounds__(256) prep_all(
    const float* __restrict__ Wq, const float* __restrict__ Wk,
    const float* __restrict__ Wv, const float* __restrict__ Wo,
    const float* __restrict__ W1, const float* __restrict__ W2,
    __half* __restrict__ bqkv, __half* __restrict__ bo,
    __half* __restrict__ b1,  __half* __restrict__ b2)
{
    int idx = blockIdx.x * 256 + threadIdx.x;
    const float* W; __half* hi;
    int K, mode, srcLd, local;
    if (idx < 3 * CQ) {
        int m = idx / CQ; local = idx - m * CQ;
        W = (m == 0) ? Wq : (m == 1) ? Wk : Wv;
        hi = bqkv + (size_t)m * 768 * 768;
        K = 768; mode = 1; srcLd = 0;
    } else if (idx < 3 * CQ + CO) {
        local = idx - 3 * CQ; W = Wo; hi = bo;
        K = 768; mode = 0; srcLd = 768;
    } else if (idx < 3 * CQ + CO + C1) {
        local = idx - 3 * CQ - CO; W = W1; hi = b1;
        K = 768; mode = 2; srcLd = 3072;
    } else {
        local = idx - 3 * CQ - CO - C1; W = W2; hi = b2;
        K = 1536; mode = 0; srcLd = 768;
    }
    int kq = K >> 2;
    int n = local / kq, k = (local - n * kq) << 2;
    int srcn = (mode == 2) ? (((n & 1) ? HALF : 0) + (n >> 1)) : n;
    union { __half b[4]; uint2 u; } H;
    #pragma unroll
    for (int j = 0; j < 4; j++) {
        size_t sa = (mode == 1)
            ? (size_t)(n >> 6) * ((size_t)K * 64) + (size_t)(k + j) * 64 + (n & 63)
            : (size_t)(k + j) * srcLd + srcn;
        H.b[j] = __float2half_rn(W[sa]);
    }
    *(uint2*)(hi + (size_t)n * K + k) = H.u;
}
#define PREP_GRID ((3*CQ + CO + C1 + C2) / 256)   // 5760

// ---------------- mma.sync fp16 GEMM ------------------------------------------
// CTA 128x128, warp 64x32, K-block 64, 2-stage cp.async.
// emode 0: C = acc + bias + resid (fp32)
// emode 1: swiglu epilogue -> Csp fp16 [M][HALF]
#define KB 64
#define PADE 72                  // fp16 elems per smem row (144 B)
#define TILEB (128*PADE*2)       // 18432
#define STGB  (2*TILEB)          // A,B per stage = 36864
#define GEMM_SMEM (2*STGB)       // 73728

__global__ void __launch_bounds__(256, 2) gemm_mma(
    const __half* __restrict__ Ap, const __half* __restrict__ Bp,
    const float* __restrict__ bias, const float* __restrict__ resid,
    float* __restrict__ C, __half* __restrict__ Csp,
    int M, int N, int K, int emode)
{
    extern __shared__ char sm[];
    int tid = threadIdx.x, lane = tid & 31, wid = tid >> 5;
    int wm = wid >> 2, wn = wid & 3;
    int bm = blockIdx.y * 128, bn = blockIdx.x * 128;
    uint32_t sbase = smem_u32(sm);

    float acc[4][4][4];
    #pragma unroll
    for (int i = 0; i < 4; i++)
        #pragma unroll
        for (int j = 0; j < 4; j++)
            #pragma unroll
            for (int q = 0; q < 4; q++) acc[i][j][q] = 0.f;

    int a_r = lane & 15, a_c = (lane & 16) ? 8 : 0;
    int b_r = ((lane >> 4) << 3) + (lane & 7), b_c = (lane & 8);
    const int KBn = K / KB;

    auto load_stage = [&](int kb, int stg) {
        #pragma unroll
        for (int t2 = 0; t2 < 2; t2++) {
            const __half* base = t2 ? Bp : Ap;
            int rowbase = t2 ? bn : bm;
            #pragma unroll
            for (int i = 0; i < 4; i++) {
                int c = i * 256 + tid;            // 0..1023
                int row = c >> 3, cc = c & 7;
                uint32_t dst = sbase + stg * STGB + t2 * TILEB
                             + (uint32_t)(row * (PADE * 2) + cc * 16);
                const __half* src =
                    base + (size_t)(rowbase + row) * K + kb * KB + cc * 8;
                CPASYNC(dst, src);
            }
        }
    };

    load_stage(0, 0);
    CPCOMMIT();

    for (int kb = 0; kb < KBn; kb++) {
        if (kb + 1 < KBn) {
            load_stage(kb + 1, (kb + 1) & 1);
            CPCOMMIT();
            CPWAIT(1);
        } else {
            CPWAIT(0);
        }
        __syncthreads();

        uint32_t sa = sbase + (kb & 1) * STGB;
        uint32_t aof = sa, bof = sa + TILEB;
        #pragma unroll
        for (int ks = 0; ks < KB; ks += 16) {
            uint32_t af[4][4], bf2[2][4];
            #pragma unroll
            for (int mt = 0; mt < 4; mt++) {
                uint32_t off = (uint32_t)(((wm * 64 + mt * 16 + a_r) * PADE + ks + a_c) * 2);
                LDSM4(af[mt], aof + off);
            }
            #pragma unroll
            for (int np = 0; np < 2; np++) {
                uint32_t off = (uint32_t)(((wn * 32 + np * 16 + b_r) * PADE + ks + b_c) * 2);
                LDSM4(bf2[np], bof + off);
            }
            #pragma unroll
            for (int mt = 0; mt < 4; mt++)
                #pragma unroll
                for (int nt = 0; nt < 4; nt++)
                    MMA16816(acc[mt][nt], af[mt],
                             bf2[nt >> 1][(nt & 1) * 2], bf2[nt >> 1][(nt & 1) * 2 + 1]);
        }
        __syncthreads();
    }

    int g = lane >> 2, t = lane & 3;
    if (emode == 0) {
        #pragma unroll
        for (int mt = 0; mt < 4; mt++) {
            #pragma unroll
            for (int half = 0; half < 2; half++) {
                int row = bm + wm * 64 + mt * 16 + g + half * 8;
                float* cp = C + (size_t)row * N;
                const float* rp = resid ? (resid + (size_t)row * N) : nullptr;
                #pragma unroll
                for (int nt = 0; nt < 4; nt++) {
                    int col = bn + wn * 32 + nt * 8 + t * 2;
                    float2 v;
                    v.x = acc[mt][nt][half * 2 + 0];
                    v.y = acc[mt][nt][half * 2 + 1];
                    if (bias) {
                        float2 b2v = *(const float2*)(bias + col);
                        v.x += b2v.x; v.y += b2v.y;
                    }
                    if (rp) {
                        float2 r2v = *(const float2*)(rp + col);
                        v.x += r2v.x; v.y += r2v.y;
                    }
                    *(float2*)(cp + col) = v;
                }
            }
        }
    } else {
        #pragma unroll
        for (int mt = 0; mt < 4; mt++) {
            #pragma unroll
            for (int half = 0; half < 2; half++) {
                int row = bm + wm * 64 + mt * 16 + g + half * 8;
                #pragma unroll
                for (int nt = 0; nt < 4; nt++) {
                    int gcol = bn + wn * 32 + nt * 8 + t * 2;
                    int j = gcol >> 1;
                    float val = acc[mt][nt][half * 2 + 0] + bias[j];
                    float gt  = acc[mt][nt][half * 2 + 1] + bias[HALF + j];
                    float s = gt / (1.0f + __expf(-gt));
                    Csp[(size_t)row * HALF + j] = __float2half_rn(s * val);
                }
            }
        }
    }
}

// ---------------- split K/V into per-head fp16 layouts ------------------------
__global__ void __launch_bounds__(256) split_kv(
    const float* __restrict__ QKV, __half* __restrict__ KBo,
    __half* __restrict__ VBo)
{
    __shared__ float vs[64][65];
    int tid = threadIdx.x;
    int tt = blockIdx.x, bh = blockIdx.y;
    int b = bh / HH, hh = bh % HH;

    #pragma unroll
    for (int i = 0; i < 8; i++) {
        int p = i * 256 + tid;
        int row = p >> 5, c = (p & 31) * 2;
        const float* s = QKV + (size_t)(b * TT + tt * 64 + row) * QKVN + DD + hh * HS + c;
        size_t o = ((size_t)bh * TT + tt * 64 + row) * HS + c;
        *(uint32_t*)(KBo + o) = packh(__float2half_rn(s[0]), __float2half_rn(s[1]));
    }
    #pragma unroll
    for (int i = 0; i < 8; i++) {
        int p = i * 256 + tid;
        int row = p >> 5, c = (p & 31) * 2;
        const float* s = QKV + (size_t)(b * TT + tt * 64 + row) * QKVN + 2 * DD + hh * HS + c;
        vs[row][c] = s[0]; vs[row][c + 1] = s[1];
    }
    __syncthreads();
    #pragma unroll
    for (int i = 0; i < 8; i++) {
        int p = i * 256 + tid;
        int c = p >> 5, t2 = (p & 31) * 2;
        size_t o = ((size_t)bh * HS + c) * TT + tt * 64 + t2;
        *(uint32_t*)(VBo + o) = packh(__float2half_rn(vs[t2][c]), __float2half_rn(vs[t2 + 1][c]));
    }
}

// ---------------- tensor-core causal flash attention (fp16) -------------------
// smem: Q 128x72 fp16 (18432) | 2 stages x [K(9216) V(9216)]
#define ATT_STG 18432
#define ATT_SMEM (18432 + 2*ATT_STG)   // 55296

__global__ void __launch_bounds__(256, 2) attn_tc(
    const float* __restrict__ QKV, const __half* __restrict__ KBi,
    const __half* __restrict__ VBi, __half* __restrict__ ATB)
{
    extern __shared__ char sm[];
    uint32_t sbase = smem_u32(sm);
    int tid = threadIdx.x, lane = tid & 31, wid = tid >> 5;
    int qt = (int)(gridDim.x - 1 - blockIdx.x);
    int bh = blockIdx.y, b = bh / HH, hh = bh % HH;
    int q0 = qt * 128;
    int nkt = 2 * qt + 2;

    int a_r = lane & 15, a_c = (lane & 16) ? 8 : 0;
    int b_r = ((lane >> 4) << 3) + (lane & 7), b_c = lane & 8;
    int g = lane >> 2, tq = lane & 3;

    auto ldkv = [&](int kt, int stg) {
        uint32_t sb2 = sbase + 18432 + stg * ATT_STG;
        size_t kbase = ((size_t)bh * TT + kt * 64) * HS;
        size_t vbase = (size_t)bh * HS * TT + kt * 64;
        #pragma unroll
        for (int i = 0; i < 4; i++) {
            int ch = i * 256 + tid;            // 0..1023
            int tile = ch >> 9;                // 0:K 1:V
            int r = (ch >> 3) & 63, cc = ch & 7;
            uint32_t dst = sb2 + tile * 9216 + r * 144 + cc * 16;
            const __half* src = (tile == 0)
                ? KBi + kbase + r * 64 + cc * 8
                : VBi + vbase + (size_t)r * TT + cc * 8;
            CPASYNC(dst, src);
        }
    };

    ldkv(0, 0);
    CPCOMMIT();

    // stage Q: scale + fp16, row stride 72
    for (int p = tid; p < 4096; p += 256) {
        int row = p >> 5, c = (p & 31) * 2;
        const float* s = QKV + (size_t)(b * TT + q0 + row) * QKVN + hh * HS + c;
        *(uint32_t*)(sm + (row * 72 + c) * 2) =
            packh(__float2half_rn(s[0] * SCL), __float2half_rn(s[1] * SCL));
    }
    __syncthreads();

    float oacc[8][4];
    #pragma unroll
    for (int n = 0; n < 8; n++)
        #pragma unroll
        for (int j = 0; j < 4; j++) oacc[n][j] = 0.f;
    float lsum0 = 0.f, lsum1 = 0.f;

    for (int kt = 0; kt < nkt; kt++) {
        if (kt + 1 < nkt) { ldkv(kt + 1, (kt + 1) & 1); CPCOMMIT(); CPWAIT(1); }
        else              { CPWAIT(0); }
        __syncthreads();

        uint32_t KHb = sbase + 18432 + (kt & 1) * ATT_STG;
        uint32_t VHb = KHb + 9216;

        float sacc[8][4];
        #pragma unroll
        for (int n = 0; n < 8; n++)
            #pragma unroll
            for (int j = 0; j < 4; j++) sacc[n][j] = 0.f;

        #pragma unroll
        for (int ks = 0; ks < 4; ks++) {
            uint32_t qh[4];
            uint32_t qa = sbase + (uint32_t)(((wid * 16 + a_r) * 72 + ks * 16 + a_c) * 2);
            LDSM4(qh, qa);
            #pragma unroll
            for (int nt2 = 0; nt2 < 4; nt2++) {
                uint32_t kf[4];
                uint32_t ka = (uint32_t)(((nt2 * 16 + b_r) * 72 + ks * 16 + b_c) * 2);
                LDSM4(kf, KHb + ka);
                MMA16816(sacc[2*nt2],     qh, kf[0], kf[1]);
                MMA16816(sacc[2*nt2 + 1], qh, kf[2], kf[3]);
            }
        }

        bool msk = (kt >= 2 * qt);
        int r0 = q0 + wid * 16 + g, r1 = r0 + 8;
        int cb = kt * 64 + tq * 2;
        #pragma unroll
        for (int n = 0; n < 8; n++) {
            #pragma unroll
            for (int j = 0; j < 4; j++) {
                int c = cb + n * 8 + (j & 1);
                int r = (j < 2) ? r0 : r1;
                sacc[n][j] = (!msk || c <= r) ? __expf(sacc[n][j]) : 0.f;
            }
        }

        #pragma unroll
        for (int pk = 0; pk < 4; pk++) {
            __half p00 = __float2half_rn(sacc[2*pk][0]);
            __half p01 = __float2half_rn(sacc[2*pk][1]);
            __half p02 = __float2half_rn(sacc[2*pk][2]);
            __half p03 = __float2half_rn(sacc[2*pk][3]);
            __half p10 = __float2half_rn(sacc[2*pk+1][0]);
            __half p11 = __float2half_rn(sacc[2*pk+1][1]);
            __half p12 = __float2half_rn(sacc[2*pk+1][2]);
            __half p13 = __float2half_rn(sacc[2*pk+1][3]);
            lsum0 += __half2float(p00) + __half2float(p01)
                   + __half2float(p10) + __half2float(p11);
            lsum1 += __half2float(p02) + __half2float(p03)
                   + __half2float(p12) + __half2float(p13);
            uint32_t pa[4];
            pa[0] = packh(p00, p01);
            pa[1] = packh(p02, p03);
            pa[2] = packh(p10, p11);
            pa[3] = packh(p12, p13);
            #pragma unroll
            for (int nt2 = 0; nt2 < 4; nt2++) {
                uint32_t vf[4];
                uint32_t va = (uint32_t)(((nt2 * 16 + b_r) * 72 + pk * 16 + b_c) * 2);
                LDSM4(vf, VHb + va);
                MMA16816(oacc[2*nt2],     pa, vf[0], vf[1]);
                MMA16816(oacc[2*nt2 + 1], pa, vf[2], vf[3]);
            }
        }
        __syncthreads();
    }

    lsum0 += __shfl_xor_sync(0xffffffffu, lsum0, 1);
    lsum0 += __shfl_xor_sync(0xffffffffu, lsum0, 2);
    lsum1 += __shfl_xor_sync(0xffffffffu, lsum1, 1);
    lsum1 += __shfl_xor_sync(0xffffffffu, lsum1, 2);
    float inv0 = 1.0f / lsum0, inv1 = 1.0f / lsum1;

    size_t rg0 = (size_t)(b * TT + q0 + wid * 16 + g);
    size_t rg1 = rg0 + 8;
    int lc = hh * HS + tq * 2;
    #pragma unroll
    for (int n = 0; n < 8; n++) {
        *(uint32_t*)(ATB + rg0 * DD + lc + n * 8) =
            packh(__float2half_rn(oacc[n][0] * inv0), __float2half_rn(oacc[n][1] * inv0));
        *(uint32_t*)(ATB + rg1 * DD + lc + n * 8) =
            packh(__float2half_rn(oacc[n][2] * inv1), __float2half_rn(oacc[n][3] * inv1));
    }
}

// ---------------- RMSNorm -> fp16 ---------------------------------------------
__global__ void __launch_bounds__(256) rmsnorm_h(
    const float* __restrict__ x, const float* __restrict__ gw,
    __half* __restrict__ o)
{
    int row = blockIdx.x;
    const float* xr = x + (size_t)row * DD;
    int tid = threadIdx.x;
    float ss = 0.f;
    for (int i = tid; i < DD; i += 256) { float v = xr[i]; ss += v * v; }
    #pragma unroll
    for (int o2 = 16; o2 > 0; o2 >>= 1) ss += __shfl_xor_sync(0xffffffffu, ss, o2);
    __shared__ float red[8];
    if ((tid & 31) == 0) red[tid >> 5] = ss;
    __syncthreads();
    if (tid < 8) {
        float v = red[tid];
        #pragma unroll
        for (int o2 = 4; o2 > 0; o2 >>= 1) v += __shfl_xor_sync(0xffu, v, o2);
        if (tid == 0) red[0] = v;
    }
    __syncthreads();
    float rms = sqrtf(red[0] * (1.0f / DD));
    float inv = 1.0f / (rms + 1e-8f);
    for (int i = tid; i < DD; i += 256)
        o[(size_t)row * DD + i] = __float2half_rn(gw[i] * xr[i] * inv);
}

// ---------------- launch -----------------------------------------------------
extern "C" void kernel_launch(void* const* d_in, const int* in_sizes, int n_in,
                              void* d_out, int out_size)
{
    const float* x  = (const float*)d_in[0];
    const float* Wq = (const float*)d_in[1];
    const float* Wk = (const float*)d_in[2];
    const float* Wv = (const float*)d_in[3];
    const float* Wo = (const float*)d_in[4];
    const float* bo = (const float*)d_in[5];
    const float* W1 = (const float*)d_in[6];
    const float* b1 = (const float*)d_in[7];
    const float* W2 = (const float*)d_in[8];
    const float* b2 = (const float*)d_in[9];
    const float* g1 = (const float*)d_in[10];
    const float* g2 = (const float*)d_in[11];
    float* out = (float*)d_out;

    float *qkv, *x1;
    __half *ah, *atb, *h2b, *swb, *kb, *vb, *bqkv, *bo_, *b1_, *b2_;
    cudaGetSymbolAddress((void**)&qkv, g_qkv);
    cudaGetSymbolAddress((void**)&x1,  g_x1);
    cudaGetSymbolAddress((void**)&ah,  g_ah);
    cudaGetSymbolAddress((void**)&atb, g_atb);
    cudaGetSymbolAddress((void**)&h2b, g_h2b);
    cudaGetSymbolAddress((void**)&swb, g_swb);
    cudaGetSymbolAddress((void**)&kb,  g_kb);
    cudaGetSymbolAddress((void**)&vb,  g_vb);
    cudaGetSymbolAddress((void**)&bqkv, g_bqkv);
    cudaGetSymbolAddress((void**)&bo_,  g_bo);
    cudaGetSymbolAddress((void**)&b1_,  g_b1);
    cudaGetSymbolAddress((void**)&b2_,  g_b2);

    cudaFuncSetAttribute(gemm_mma, cudaFuncAttributeMaxDynamicSharedMemorySize, GEMM_SMEM);
    cudaFuncSetAttribute(attn_tc,  cudaFuncAttributeMaxDynamicSharedMemorySize, ATT_SMEM);

    // 0) all weight prep in one launch
    prep_all<<<PREP_GRID, 256>>>(Wq, Wk, Wv, Wo, W1, W2, bqkv, bo_, b1_, b2_);

    // 1) ah = fp16(rmsnorm(x, g1))
    rmsnorm_h<<<NT, 256>>>(x, g1, ah);

    // 2) qkv = ah @ [Wq|Wk|Wv]
    gemm_mma<<<dim3(QKVN / 128, NT / 128), 256, GEMM_SMEM>>>(
        ah, bqkv, nullptr, nullptr, qkv, nullptr, NT, QKVN, DD, 0);

    // 3) K/V per-head fp16 layouts
    split_kv<<<dim3(TT / 64, BH), 256>>>(qkv, kb, vb);

    // 4) attention -> atb (fp16)
    attn_tc<<<dim3(TT / 128, BH), 256, ATT_SMEM>>>(qkv, kb, vb, atb);

    // 5) x1 = x + atb @ Wo + bo
    gemm_mma<<<dim3(DD / 128, NT / 128), 256, GEMM_SMEM>>>(
        atb, bo_, bo, x, x1, nullptr, NT, DD, DD, 0);

    // 6) h2b = fp16(rmsnorm(x1, g2))
    rmsnorm_h<<<NT, 256>>>(x1, g2, h2b);

    // 7) swb = swiglu(h2b @ W1' + b1)  — fused epilogue, interleaved W1
    gemm_mma<<<dim3(FF / 128, NT / 128), 256, GEMM_SMEM>>>(
        h2b, b1_, b1, nullptr, nullptr, swb, NT, FF, DD, 1);

    // 8) out = x1 + swb @ W2 + b2
    gemm_mma<<<dim3(DD / 128, NT / 128), 256, GEMM_SMEM>>>(
        swb, b2_, b2, x1, out, nullptr, NT, DD, HALF, 0);
}

// round 8
// speedup vs baseline: 2.2452x; 1.0372x over previous
#include <cuda_runtime.h>
#include <cuda_fp16.h>
#include <cstdint>
#include <cstddef>

// Problem constants
#define BB 2
#define TT 2048
#define DD 768
#define HH 12
#define HS 64
#define FF 3072
#define HALF 1536
#define NT (BB*TT)       // 4096
#define QKVN 2304        // fused q|k|v output width
#define BH 24            // B*H
#define SCL 0.03608439182435161f   // 768^-0.5

// ---------------- scratch (device globals) -----------------------------------
__device__ float g_x1 [(size_t)NT*DD];
// fp16 activations
__device__ __half g_ah [(size_t)NT*DD];    // rmsnorm1 out
__device__ __half g_qh [(size_t)NT*DD];    // Q (pre-scaled), from QKV epilogue
__device__ __half g_atb[(size_t)NT*DD];    // attention out
__device__ __half g_h2b[(size_t)NT*DD];    // rmsnorm2 out
__device__ __half g_swb[(size_t)NT*HALF];  // swiglu out (from W1 epi)
// per-head K/V: K [bh][t][64] ; V transposed [bh][hs][T]  (from QKV epilogue)
__device__ __half g_kb [(size_t)BH*TT*HS];
__device__ __half g_vb [(size_t)BH*TT*HS];
// fp16 weights, layout [N][K]
__device__ __half g_bqkv[(size_t)QKVN*DD];
__device__ __half g_bo  [(size_t)DD*DD];
__device__ __half g_b1  [(size_t)FF*DD];   // column-interleaved (val,gate)
__device__ __half g_b2  [(size_t)DD*HALF];

// ---------------- helpers ----------------------------------------------------
__device__ __forceinline__ uint32_t smem_u32(const void* p) {
    uint32_t a;
    asm("{ .reg .u64 t; cvta.to.shared.u64 t, %1; cvt.u32.u64 %0, t; }" : "=r"(a) : "l"(p));
    return a;
}
#define CPASYNC(d, s) asm volatile("cp.async.cg.shared.global [%0], [%1], 16;" :: "r"(d), "l"(s) : "memory")
#define CPCOMMIT()    asm volatile("cp.async.commit_group;" ::: "memory")
#define CPWAIT(n)     asm volatile("cp.async.wait_group %0;" :: "n"(n) : "memory")
#define LDSM4(r, a)                                                              \
    asm volatile("ldmatrix.sync.aligned.m8n8.x4.shared.b16 {%0,%1,%2,%3}, [%4];" \
        : "=r"((r)[0]), "=r"((r)[1]), "=r"((r)[2]), "=r"((r)[3]) : "r"(a))
#define MMA16816(c, a, b0, b1)                                                   \
    asm volatile("mma.sync.aligned.m16n8k16.row.col.f32.f16.f16.f32 "            \
        "{%0,%1,%2,%3}, {%4,%5,%6,%7}, {%8,%9}, {%0,%1,%2,%3};"                  \
        : "+f"((c)[0]), "+f"((c)[1]), "+f"((c)[2]), "+f"((c)[3])                 \
        : "r"((a)[0]), "r"((a)[1]), "r"((a)[2]), "r"((a)[3]), "r"(b0), "r"(b1))

__device__ __forceinline__ uint32_t packh(__half a, __half b) {
    return (uint32_t)__half_as_ushort(a) | ((uint32_t)__half_as_ushort(b) << 16);
}

// ---------------- fused weight prep (single launch) ---------------------------
#define CQ (768*192)
#define CO (768*192)
#define C1 (3072*192)
#define C2 (768*384)

__global__ void __launch_bounds__(256) prep_all(
    const float* __restrict__ Wq, const float* __restrict__ Wk,
    const float* __restrict__ Wv, const float* __restrict__ Wo,
    const float* __restrict__ W1, const float* __restrict__ W2,
    __half* __restrict__ bqkv, __half* __restrict__ bo,
    __half* __restrict__ b1,  __half* __restrict__ b2)
{
    int idx = blockIdx.x * 256 + threadIdx.x;
    const float* W; __half* hi;
    int K, mode, srcLd, local;
    if (idx < 3 * CQ) {
        int m = idx / CQ; local = idx - m * CQ;
        W = (m == 0) ? Wq : (m == 1) ? Wk : Wv;
        hi = bqkv + (size_t)m * 768 * 768;
        K = 768; mode = 1; srcLd = 0;
    } else if (idx < 3 * CQ + CO) {
        local = idx - 3 * CQ; W = Wo; hi = bo;
        K = 768; mode = 0; srcLd = 768;
    } else if (idx < 3 * CQ + CO + C1) {
        local = idx - 3 * CQ - CO; W = W1; hi = b1;
        K = 768; mode = 2; srcLd = 3072;
    } else {
        local = idx - 3 * CQ - CO - C1; W = W2; hi = b2;
        K = 1536; mode = 0; srcLd = 768;
    }
    int kq = K >> 2;
    int n = local / kq, k = (local - n * kq) << 2;
    int srcn = (mode == 2) ? (((n & 1) ? HALF : 0) + (n >> 1)) : n;
    union { __half b[4]; uint2 u; } H;
    #pragma unroll
    for (int j = 0; j < 4; j++) {
        size_t sa = (mode == 1)
            ? (size_t)(n >> 6) * ((size_t)K * 64) + (size_t)(k + j) * 64 + (n & 63)
            : (size_t)(k + j) * srcLd + srcn;
        H.b[j] = __float2half_rn(W[sa]);
    }
    *(uint2*)(hi + (size_t)n * K + k) = H.u;
}
#define PREP_GRID ((3*CQ + CO + C1 + C2) / 256)   // 5760

// ---------------- mma.sync fp16 GEMM ------------------------------------------
// CTA 128x128, warp 64x32, K-block 64, 2-stage cp.async, ONE sync per k-block.
// emode 0: C = acc + bias + resid (fp32)
// emode 1: swiglu epilogue -> Csp fp16 [M][HALF]
// emode 2: QKV epilogue -> Q (scaled fp16, Csp), K [bh][t][64], V^T [bh][hs][T]
#define KB 64
#define PADE 72                  // fp16 elems per smem row (144 B)
#define TILEB (128*PADE*2)       // 18432
#define STGB  (2*TILEB)          // A,B per stage = 36864
#define GEMM_SMEM (2*STGB)       // 73728

__global__ void __launch_bounds__(256, 2) gemm_mma(
    const __half* __restrict__ Ap, const __half* __restrict__ Bp,
    const float* __restrict__ bias, const float* __restrict__ resid,
    float* __restrict__ C, __half* __restrict__ Csp,
    __half* __restrict__ Kout, __half* __restrict__ Vout,
    int M, int N, int K, int emode)
{
    extern __shared__ char sm[];
    int tid = threadIdx.x, lane = tid & 31, wid = tid >> 5;
    int wm = wid >> 2, wn = wid & 3;
    int bm = blockIdx.y * 128, bn = blockIdx.x * 128;
    uint32_t sbase = smem_u32(sm);

    float acc[4][4][4];
    #pragma unroll
    for (int i = 0; i < 4; i++)
        #pragma unroll
        for (int j = 0; j < 4; j++)
            #pragma unroll
            for (int q = 0; q < 4; q++) acc[i][j][q] = 0.f;

    int a_r = lane & 15, a_c = (lane & 16) ? 8 : 0;
    int b_r = ((lane >> 4) << 3) + (lane & 7), b_c = (lane & 8);
    const int KBn = K / KB;

    auto load_stage = [&](int kb, int stg) {
        #pragma unroll
        for (int t2 = 0; t2 < 2; t2++) {
            const __half* base = t2 ? Bp : Ap;
            int rowbase = t2 ? bn : bm;
            #pragma unroll
            for (int i = 0; i < 4; i++) {
                int c = i * 256 + tid;            // 0..1023
                int row = c >> 3, cc = c & 7;
                uint32_t dst = sbase + stg * STGB + t2 * TILEB
                             + (uint32_t)(row * (PADE * 2) + cc * 16);
                const __half* src =
                    base + (size_t)(rowbase + row) * K + kb * KB + cc * 8;
                CPASYNC(dst, src);
            }
        }
    };

    load_stage(0, 0);
    CPCOMMIT();

    for (int kb = 0; kb < KBn; kb++) {
        CPWAIT(0);
        __syncthreads();                 // publishes stage kb; proves kb-1 consumed
        if (kb + 1 < KBn) { load_stage(kb + 1, (kb + 1) & 1); CPCOMMIT(); }

        uint32_t sa = sbase + (kb & 1) * STGB;
        uint32_t aof = sa, bof = sa + TILEB;
        #pragma unroll
        for (int ks = 0; ks < KB; ks += 16) {
            uint32_t af[4][4], bf2[2][4];
            #pragma unroll
            for (int mt = 0; mt < 4; mt++) {
                uint32_t off = (uint32_t)(((wm * 64 + mt * 16 + a_r) * PADE + ks + a_c) * 2);
                LDSM4(af[mt], aof + off);
            }
            #pragma unroll
            for (int np = 0; np < 2; np++) {
                uint32_t off = (uint32_t)(((wn * 32 + np * 16 + b_r) * PADE + ks + b_c) * 2);
                LDSM4(bf2[np], bof + off);
            }
            #pragma unroll
            for (int mt = 0; mt < 4; mt++)
                #pragma unroll
                for (int nt = 0; nt < 4; nt++)
                    MMA16816(acc[mt][nt], af[mt],
                             bf2[nt >> 1][(nt & 1) * 2], bf2[nt >> 1][(nt & 1) * 2 + 1]);
        }
    }

    int g = lane >> 2, t = lane & 3;
    if (emode == 0) {
        #pragma unroll
        for (int mt = 0; mt < 4; mt++) {
            #pragma unroll
            for (int half = 0; half < 2; half++) {
                int row = bm + wm * 64 + mt * 16 + g + half * 8;
                float* cp = C + (size_t)row * N;
                const float* rp = resid ? (resid + (size_t)row * N) : nullptr;
                #pragma unroll
                for (int nt = 0; nt < 4; nt++) {
                    int col = bn + wn * 32 + nt * 8 + t * 2;
                    float2 v;
                    v.x = acc[mt][nt][half * 2 + 0];
                    v.y = acc[mt][nt][half * 2 + 1];
                    if (bias) {
                        float2 b2v = *(const float2*)(bias + col);
                        v.x += b2v.x; v.y += b2v.y;
                    }
                    if (rp) {
                        float2 r2v = *(const float2*)(rp + col);
                        v.x += r2v.x; v.y += r2v.y;
                    }
                    *(float2*)(cp + col) = v;
                }
            }
        }
    } else if (emode == 1) {
        #pragma unroll
        for (int mt = 0; mt < 4; mt++) {
            #pragma unroll
            for (int half = 0; half < 2; half++) {
                int row = bm + wm * 64 + mt * 16 + g + half * 8;
                #pragma unroll
                for (int nt = 0; nt < 4; nt++) {
                    int gcol = bn + wn * 32 + nt * 8 + t * 2;
                    int j = gcol >> 1;
                    float val = acc[mt][nt][half * 2 + 0] + bias[j];
                    float gt  = acc[mt][nt][half * 2 + 1] + bias[HALF + j];
                    float s = gt / (1.0f + __expf(-gt));
                    Csp[(size_t)row * HALF + j] = __float2half_rn(s * val);
                }
            }
        }
    } else {
        // QKV epilogue: bn selects region (Q / K / V), uniform per CTA
        #pragma unroll
        for (int mt = 0; mt < 4; mt++) {
            #pragma unroll
            for (int half = 0; half < 2; half++) {
                int row = bm + wm * 64 + mt * 16 + g + half * 8;
                int bq = row >> 11, t2 = row & (TT - 1);
                #pragma unroll
                for (int nt = 0; nt < 4; nt++) {
                    int col = bn + wn * 32 + nt * 8 + t * 2;
                    float vx = acc[mt][nt][half * 2 + 0];
                    float vy = acc[mt][nt][half * 2 + 1];
                    if (col < DD) {
                        *(uint32_t*)(Csp + (size_t)row * DD + col) =
                            packh(__float2half_rn(vx * SCL), __float2half_rn(vy * SCL));
                    } else if (col < 2 * DD) {
                        int c = col - DD; int h2 = c >> 6, hs = c & 63;
                        *(uint32_t*)(Kout + (((size_t)(bq * HH + h2) * TT + t2) << 6) + hs) =
                            packh(__float2half_rn(vx), __float2half_rn(vy));
                    } else {
                        int c = col - 2 * DD; int h2 = c >> 6, hs = c & 63;
                        size_t a0 = ((size_t)(bq * HH + h2) * 64 + hs) * TT + t2;
                        Vout[a0]      = __float2half_rn(vx);
                        Vout[a0 + TT] = __float2half_rn(vy);
                    }
                }
            }
        }
    }
}

// ---------------- tensor-core causal flash attention (fp16) -------------------
// smem: Q 128x72 fp16 (18432) | 3-stage ring x [K(9216) V(9216)] = 18432/stage
#define ATT_STG 18432
#define ATT_SMEM (18432 + 3*ATT_STG)   // 73728

__global__ void __launch_bounds__(256, 2) attn_tc(
    const __half* __restrict__ Qb, const __half* __restrict__ KBi,
    const __half* __restrict__ VBi, __half* __restrict__ ATB)
{
    extern __shared__ char sm[];
    uint32_t sbase = smem_u32(sm);
    int tid = threadIdx.x, lane = tid & 31, wid = tid >> 5;
    int qt = (int)(gridDim.x - 1 - blockIdx.x);
    int bh = blockIdx.y, b = bh / HH, hh = bh % HH;
    int q0 = qt * 128;
    int nkt = 2 * qt + 2;

    int a_r = lane & 15, a_c = (lane & 16) ? 8 : 0;
    int b_r = ((lane >> 4) << 3) + (lane & 7), b_c = lane & 8;
    int g = lane >> 2, tq = lane & 3;

    auto ldkv = [&](int kt, int stg) {
        uint32_t sb2 = sbase + 18432 + stg * ATT_STG;
        size_t kbase = ((size_t)bh * TT + kt * 64) * HS;
        size_t vbase = (size_t)bh * HS * TT + kt * 64;
        #pragma unroll
        for (int i = 0; i < 4; i++) {
            int ch = i * 256 + tid;            // 0..1023
            int tile = ch >> 9;                // 0:K 1:V
            int r = (ch >> 3) & 63, cc = ch & 7;
            uint32_t dst = sb2 + tile * 9216 + r * 144 + cc * 16;
            const __half* src = (tile == 0)
                ? KBi + kbase + r * 64 + cc * 8
                : VBi + vbase + (size_t)r * TT + cc * 8;
            CPASYNC(dst, src);
        }
    };

    // prologue: Q (own group), then first two K/V stages
    #pragma unroll
    for (int i = 0; i < 4; i++) {
        int p = i * 256 + tid;
        int row = p >> 3, cc = p & 7;
        CPASYNC(sbase + (uint32_t)(row * 144 + cc * 16),
                Qb + (size_t)(b * TT + q0 + row) * DD + hh * HS + cc * 8);
    }
    CPCOMMIT();
    ldkv(0, 0); CPCOMMIT();
    ldkv(1, 1); CPCOMMIT();

    float oacc[8][4];
    #pragma unroll
    for (int n = 0; n < 8; n++)
        #pragma unroll
        for (int j = 0; j < 4; j++) oacc[n][j] = 0.f;
    float lsum0 = 0.f, lsum1 = 0.f;

    for (int kt = 0; kt < nkt; kt++) {
        if (kt + 1 < nkt) { CPWAIT(1); } else { CPWAIT(0); }
        __syncthreads();                 // publishes stage kt; proves kt-1 consumed
        if (kt + 2 < nkt) { ldkv(kt + 2, (kt + 2) % 3); CPCOMMIT(); }

        uint32_t KHb = sbase + 18432 + (kt % 3) * ATT_STG;
        uint32_t VHb = KHb + 9216;

        float sacc[8][4];
        #pragma unroll
        for (int n = 0; n < 8; n++)
            #pragma unroll
            for (int j = 0; j < 4; j++) sacc[n][j] = 0.f;

        #pragma unroll
        for (int ks = 0; ks < 4; ks++) {
            uint32_t qh[4];
            uint32_t qa = sbase + (uint32_t)(((wid * 16 + a_r) * 72 + ks * 16 + a_c) * 2);
            LDSM4(qh, qa);
            #pragma unroll
            for (int nt2 = 0; nt2 < 4; nt2++) {
                uint32_t kf[4];
                uint32_t ka = (uint32_t)(((nt2 * 16 + b_r) * 72 + ks * 16 + b_c) * 2);
                LDSM4(kf, KHb + ka);
                MMA16816(sacc[2*nt2],     qh, kf[0], kf[1]);
                MMA16816(sacc[2*nt2 + 1], qh, kf[2], kf[3]);
            }
        }

        bool msk = (kt >= 2 * qt);
        int r0 = q0 + wid * 16 + g, r1 = r0 + 8;
        int cb = kt * 64 + tq * 2;
        #pragma unroll
        for (int n = 0; n < 8; n++) {
            #pragma unroll
            for (int j = 0; j < 4; j++) {
                int c = cb + n * 8 + (j & 1);
                int r = (j < 2) ? r0 : r1;
                sacc[n][j] = (!msk || c <= r) ? __expf(sacc[n][j]) : 0.f;
            }
        }

        #pragma unroll
        for (int pk = 0; pk < 4; pk++) {
            __half p00 = __float2half_rn(sacc[2*pk][0]);
            __half p01 = __float2half_rn(sacc[2*pk][1]);
            __half p02 = __float2half_rn(sacc[2*pk][2]);
            __half p03 = __float2half_rn(sacc[2*pk][3]);
            __half p10 = __float2half_rn(sacc[2*pk+1][0]);
            __half p11 = __float2half_rn(sacc[2*pk+1][1]);
            __half p12 = __float2half_rn(sacc[2*pk+1][2]);
            __half p13 = __float2half_rn(sacc[2*pk+1][3]);
            lsum0 += __half2float(p00) + __half2float(p01)
                   + __half2float(p10) + __half2float(p11);
            lsum1 += __half2float(p02) + __half2float(p03)
                   + __half2float(p12) + __half2float(p13);
            uint32_t pa[4];
            pa[0] = packh(p00, p01);
            pa[1] = packh(p02, p03);
            pa[2] = packh(p10, p11);
            pa[3] = packh(p12, p13);
            #pragma unroll
            for (int nt2 = 0; nt2 < 4; nt2++) {
                uint32_t vf[4];
                uint32_t va = (uint32_t)(((nt2 * 16 + b_r) * 72 + pk * 16 + b_c) * 2);
                LDSM4(vf, VHb + va);
                MMA16816(oacc[2*nt2],     pa, vf[0], vf[1]);
                MMA16816(oacc[2*nt2 + 1], pa, vf[2], vf[3]);
            }
        }
    }

    lsum0 += __shfl_xor_sync(0xffffffffu, lsum0, 1);
    lsum0 += __shfl_xor_sync(0xffffffffu, lsum0, 2);
    lsum1 += __shfl_xor_sync(0xffffffffu, lsum1, 1);
    lsum1 += __shfl_xor_sync(0xffffffffu, lsum1, 2);
    float inv0 = 1.0f / lsum0, inv1 = 1.0f / lsum1;

    size_t rg0 = (size_t)(b * TT + q0 + wid * 16 + g);
    size_t rg1 = rg0 + 8;
    int lc = hh * HS + tq * 2;
    #pragma unroll
    for (int n = 0; n < 8; n++) {
        *(uint32_t*)(ATB + rg0 * DD + lc + n * 8) =
            packh(__float2half_rn(oacc[n][0] * inv0), __float2half_rn(oacc[n][1] * inv0));
        *(uint32_t*)(ATB + rg1 * DD + lc + n * 8) =
            packh(__float2half_rn(oacc[n][2] * inv1), __float2half_rn(oacc[n][3] * inv1));
    }
}

// ---------------- RMSNorm -> fp16 ---------------------------------------------
__global__ void __launch_bounds__(256) rmsnorm_h(
    const float* __restrict__ x, const float* __restrict__ gw,
    __half* __restrict__ o)
{
    int row = blockIdx.x;
    const float* xr = x + (size_t)row * DD;
    int tid = threadIdx.x;
    float ss = 0.f;
    for (int i = tid; i < DD; i += 256) { float v = xr[i]; ss += v * v; }
    #pragma unroll
    for (int o2 = 16; o2 > 0; o2 >>= 1) ss += __shfl_xor_sync(0xffffffffu, ss, o2);
    __shared__ float red[8];
    if ((tid & 31) == 0) red[tid >> 5] = ss;
    __syncthreads();
    if (tid < 8) {
        float v = red[tid];
        #pragma unroll
        for (int o2 = 4; o2 > 0; o2 >>= 1) v += __shfl_xor_sync(0xffu, v, o2);
        if (tid == 0) red[0] = v;
    }
    __syncthreads();
    float rms = sqrtf(red[0] * (1.0f / DD));
    float inv = 1.0f / (rms + 1e-8f);
    for (int i = tid; i < DD; i += 256)
        o[(size_t)row * DD + i] = __float2half_rn(gw[i] * xr[i] * inv);
}

// ---------------- launch -----------------------------------------------------
extern "C" void kernel_launch(void* const* d_in, const int* in_sizes, int n_in,
                              void* d_out, int out_size)
{
    const float* x  = (const float*)d_in[0];
    const float* Wq = (const float*)d_in[1];
    const float* Wk = (const float*)d_in[2];
    const float* Wv = (const float*)d_in[3];
    const float* Wo = (const float*)d_in[4];
    const float* bo = (const float*)d_in[5];
    const float* W1 = (const float*)d_in[6];
    const float* b1 = (const float*)d_in[7];
    const float* W2 = (const float*)d_in[8];
    const float* b2 = (const float*)d_in[9];
    const float* g1 = (const float*)d_in[10];
    const float* g2 = (const float*)d_in[11];
    float* out = (float*)d_out;

    float *x1;
    __half *ah, *qh, *atb, *h2b, *swb, *kb, *vb, *bqkv, *bo_, *b1_, *b2_;
    cudaGetSymbolAddress((void**)&x1,  g_x1);
    cudaGetSymbolAddress((void**)&ah,  g_ah);
    cudaGetSymbolAddress((void**)&qh,  g_qh);
    cudaGetSymbolAddress((void**)&atb, g_atb);
    cudaGetSymbolAddress((void**)&h2b, g_h2b);
    cudaGetSymbolAddress((void**)&swb, g_swb);
    cudaGetSymbolAddress((void**)&kb,  g_kb);
    cudaGetSymbolAddress((void**)&vb,  g_vb);
    cudaGetSymbolAddress((void**)&bqkv, g_bqkv);
    cudaGetSymbolAddress((void**)&bo_,  g_bo);
    cudaGetSymbolAddress((void**)&b1_,  g_b1);
    cudaGetSymbolAddress((void**)&b2_,  g_b2);

    cudaFuncSetAttribute(gemm_mma, cudaFuncAttributeMaxDynamicSharedMemorySize, GEMM_SMEM);
    cudaFuncSetAttribute(attn_tc,  cudaFuncAttributeMaxDynamicSharedMemorySize, ATT_SMEM);

    // 0) all weight prep in one launch
    prep_all<<<PREP_GRID, 256>>>(Wq, Wk, Wv, Wo, W1, W2, bqkv, bo_, b1_, b2_);

    // 1) ah = fp16(rmsnorm(x, g1))
    rmsnorm_h<<<NT, 256>>>(x, g1, ah);

    // 2) qkv GEMM: epilogue scatters Q (scaled fp16), K, V^T per-head directly
    gemm_mma<<<dim3(QKVN / 128, NT / 128), 256, GEMM_SMEM>>>(
        ah, bqkv, nullptr, nullptr, nullptr, qh, kb, vb, NT, QKVN, DD, 2);

    // 3) attention -> atb (fp16)
    attn_tc<<<dim3(TT / 128, BH), 256, ATT_SMEM>>>(qh, kb, vb, atb);

    // 4) x1 = x + atb @ Wo + bo
    gemm_mma<<<dim3(DD / 128, NT / 128), 256, GEMM_SMEM>>>(
        atb, bo_, bo, x, x1, nullptr, nullptr, nullptr, NT, DD, DD, 0);

    // 5) h2b = fp16(rmsnorm(x1, g2))
    rmsnorm_h<<<NT, 256>>>(x1, g2, h2b);

    // 6) swb = swiglu(h2b @ W1' + b1)  — fused epilogue, interleaved W1
    gemm_mma<<<dim3(FF / 128, NT / 128), 256, GEMM_SMEM>>>(
        h2b, b1_, b1, nullptr, nullptr, swb, nullptr, nullptr, NT, FF, DD, 1);

    // 7) out = x1 + swb @ W2 + b2
    gemm_mma<<<dim3(DD / 128, NT / 128), 256, GEMM_SMEM>>>(
        swb, b2_, b2, x1, out, nullptr, nullptr, nullptr, NT, DD, HALF, 0);
}

// round 9
// speedup vs baseline: 2.3190x; 1.0328x over previous
#include <cuda_runtime.h>
#include <cuda_fp16.h>
#include <cstdint>
#include <cstddef>

// Problem constants
#define BB 2
#define TT 2048
#define DD 768
#define HH 12
#define HS 64
#define FF 3072
#define HALF 1536
#define NT (BB*TT)       // 4096
#define QKVN 2304        // fused q|k|v output width
#define BH 24            // B*H
#define SCL 0.03608439182435161f   // 768^-0.5

// ---------------- scratch (device globals) -----------------------------------
__device__ float g_x1 [(size_t)NT*DD];
__device__ __half g_ah [(size_t)NT*DD];    // rmsnorm1 out
__device__ __half g_qh [(size_t)NT*DD];    // Q (pre-scaled), from QKV epilogue
__device__ __half g_atb[(size_t)NT*DD];    // attention out
__device__ __half g_h2b[(size_t)NT*DD];    // rmsnorm2 out
__device__ __half g_swb[(size_t)NT*HALF];  // swiglu out (from W1 epi)
__device__ __half g_kb [(size_t)BH*TT*HS]; // K [bh][t][64]
__device__ __half g_vb [(size_t)BH*TT*HS]; // V^T [bh][hs][T]
// fp16 weights, layout [N][K]
__device__ __half g_bqkv[(size_t)QKVN*DD];
__device__ __half g_bo  [(size_t)DD*DD];
__device__ __half g_b1  [(size_t)FF*DD];   // column-interleaved (val,gate)
__device__ __half g_b2  [(size_t)DD*HALF];

// ---------------- helpers ----------------------------------------------------
__device__ __forceinline__ uint32_t smem_u32(const void* p) {
    uint32_t a;
    asm("{ .reg .u64 t; cvta.to.shared.u64 t, %1; cvt.u32.u64 %0, t; }" : "=r"(a) : "l"(p));
    return a;
}
#define CPASYNC(d, s) asm volatile("cp.async.cg.shared.global [%0], [%1], 16;" :: "r"(d), "l"(s) : "memory")
#define CPCOMMIT()    asm volatile("cp.async.commit_group;" ::: "memory")
#define CPWAIT(n)     asm volatile("cp.async.wait_group %0;" :: "n"(n) : "memory")
#define LDSM4(r, a)                                                              \
    asm volatile("ldmatrix.sync.aligned.m8n8.x4.shared.b16 {%0,%1,%2,%3}, [%4];" \
        : "=r"((r)[0]), "=r"((r)[1]), "=r"((r)[2]), "=r"((r)[3]) : "r"(a))
#define MMA16816(c, a, b0, b1)                                                   \
    asm volatile("mma.sync.aligned.m16n8k16.row.col.f32.f16.f16.f32 "            \
        "{%0,%1,%2,%3}, {%4,%5,%6,%7}, {%8,%9}, {%0,%1,%2,%3};"                  \
        : "+f"((c)[0]), "+f"((c)[1]), "+f"((c)[2]), "+f"((c)[3])                 \
        : "r"((a)[0]), "r"((a)[1]), "r"((a)[2]), "r"((a)[3]), "r"(b0), "r"(b1))

__device__ __forceinline__ uint32_t packh(__half a, __half b) {
    return (uint32_t)__half_as_ushort(a) | ((uint32_t)__half_as_ushort(b) << 16);
}

// ---------------- coalesced weight prep: smem tile transpose -------------------
// 32x32 tiles; reads coalesced from fp32 src, writes coalesced fp16 [N][K].
// modes: 0 = plain [K][N] (srcLd), 1 = qkv head layout, 2 = W1 interleaved cols
__global__ void __launch_bounds__(256) prep_tr(
    const float* __restrict__ Wq, const float* __restrict__ Wk,
    const float* __restrict__ Wv, const float* __restrict__ Wo,
    const float* __restrict__ W1, const float* __restrict__ W2,
    __half* __restrict__ bqkv, __half* __restrict__ bo,
    __half* __restrict__ b1,  __half* __restrict__ b2)
{
    __shared__ float ts[32][33];
    int bid = blockIdx.x;
    int tx = threadIdx.x & 31, ty = threadIdx.x >> 5;

    const float* W; __half* dst;
    int K, mode, srcLd, tn, tk;
    if (bid < 2304) {                       // Wq,Wk,Wv (mode1) + Wo (mode0)
        int m = bid / 576, lt = bid - m * 576;
        W = (m == 0) ? Wq : (m == 1) ? Wk : (m == 2) ? Wv : Wo;
        dst = (m < 3) ? bqkv + (size_t)m * 768 * 768 : bo;
        K = 768; mode = (m < 3) ? 1 : 0; srcLd = 768;
        tn = lt / 24; tk = lt - (lt / 24) * 24;
    } else if (bid < 4608) {                // W1 interleaved
        int lt = bid - 2304;
        W = W1; dst = b1; K = 768; mode = 2; srcLd = 3072;
        tn = lt / 24; tk = lt - (lt / 24) * 24;
    } else {                                // W2
        int lt = bid - 4608;
        W = W2; dst = b2; K = 1536; mode = 0; srcLd = 768;
        tn = lt / 48; tk = lt - (lt / 48) * 48;
    }
    int k0 = tk * 32, n0 = tn * 32;

    #pragma unroll
    for (int i = 0; i < 4; i++) {
        int kk = ty + i * 8;
        float v; int col;
        if (mode == 0) {
            v = W[(size_t)(k0 + kk) * srcLd + n0 + tx];
            col = tx;
        } else if (mode == 1) {
            v = W[(size_t)(n0 >> 6) * (768 * 64) + (size_t)(k0 + kk) * 64 + (n0 & 63) + tx];
            col = tx;
        } else {
            int j = tx & 15, grp = tx >> 4;
            v = W[(size_t)(k0 + kk) * 3072 + (grp ? HALF : 0) + (n0 >> 1) + j];
            col = 2 * j + grp;              // even cols = value, odd = gate
        }
        ts[kk][col] = v;
    }
    __syncthreads();
    #pragma unroll
    for (int i = 0; i < 4; i++) {
        int nn = ty + i * 8;
        dst[(size_t)(n0 + nn) * K + k0 + tx] = __float2half_rn(ts[tx][nn]);
    }
}
#define PREP_GRID 5760

// ---------------- mma.sync fp16 GEMM ------------------------------------------
// CTA 128x128, warp 64x32, K-block 64, 2-stage cp.async, one sync per k-block.
// emode 0: C = acc + bias + resid (fp32); 1: swiglu -> Csp; 2: QKV scatter
#define KB 64
#define PADE 72
#define TILEB (128*PADE*2)
#define STGB  (2*TILEB)
#define GEMM_SMEM (2*STGB)

__global__ void __launch_bounds__(256, 2) gemm_mma(
    const __half* __restrict__ Ap, const __half* __restrict__ Bp,
    const float* __restrict__ bias, const float* __restrict__ resid,
    float* __restrict__ C, __half* __restrict__ Csp,
    __half* __restrict__ Kout, __half* __restrict__ Vout,
    int M, int N, int K, int emode)
{
    extern __shared__ char sm[];
    int tid = threadIdx.x, lane = tid & 31, wid = tid >> 5;
    int wm = wid >> 2, wn = wid & 3;
    int bm = blockIdx.y * 128, bn = blockIdx.x * 128;
    uint32_t sbase = smem_u32(sm);

    float acc[4][4][4];
    #pragma unroll
    for (int i = 0; i < 4; i++)
        #pragma unroll
        for (int j = 0; j < 4; j++)
            #pragma unroll
            for (int q = 0; q < 4; q++) acc[i][j][q] = 0.f;

    int a_r = lane & 15, a_c = (lane & 16) ? 8 : 0;
    int b_r = ((lane >> 4) << 3) + (lane & 7), b_c = (lane & 8);
    const int KBn = K / KB;

    auto load_stage = [&](int kb, int stg) {
        #pragma unroll
        for (int t2 = 0; t2 < 2; t2++) {
            const __half* base = t2 ? Bp : Ap;
            int rowbase = t2 ? bn : bm;
            #pragma unroll
            for (int i = 0; i < 4; i++) {
                int c = i * 256 + tid;
                int row = c >> 3, cc = c & 7;
                uint32_t dst = sbase + stg * STGB + t2 * TILEB
                             + (uint32_t)(row * (PADE * 2) + cc * 16);
                const __half* src =
                    base + (size_t)(rowbase + row) * K + kb * KB + cc * 8;
                CPASYNC(dst, src);
            }
        }
    };

    load_stage(0, 0);
    CPCOMMIT();

    for (int kb = 0; kb < KBn; kb++) {
        CPWAIT(0);
        __syncthreads();
        if (kb + 1 < KBn) { load_stage(kb + 1, (kb + 1) & 1); CPCOMMIT(); }

        uint32_t sa = sbase + (kb & 1) * STGB;
        uint32_t aof = sa, bof = sa + TILEB;
        #pragma unroll
        for (int ks = 0; ks < KB; ks += 16) {
            uint32_t af[4][4], bf2[2][4];
            #pragma unroll
            for (int mt = 0; mt < 4; mt++) {
                uint32_t off = (uint32_t)(((wm * 64 + mt * 16 + a_r) * PADE + ks + a_c) * 2);
                LDSM4(af[mt], aof + off);
            }
            #pragma unroll
            for (int np = 0; np < 2; np++) {
                uint32_t off = (uint32_t)(((wn * 32 + np * 16 + b_r) * PADE + ks + b_c) * 2);
                LDSM4(bf2[np], bof + off);
            }
            #pragma unroll
            for (int mt = 0; mt < 4; mt++)
                #pragma unroll
                for (int nt = 0; nt < 4; nt++)
                    MMA16816(acc[mt][nt], af[mt],
                             bf2[nt >> 1][(nt & 1) * 2], bf2[nt >> 1][(nt & 1) * 2 + 1]);
        }
    }

    int g = lane >> 2, t = lane & 3;
    if (emode == 0) {
        #pragma unroll
        for (int mt = 0; mt < 4; mt++) {
            #pragma unroll
            for (int half = 0; half < 2; half++) {
                int row = bm + wm * 64 + mt * 16 + g + half * 8;
                float* cp = C + (size_t)row * N;
                const float* rp = resid ? (resid + (size_t)row * N) : nullptr;
                #pragma unroll
                for (int nt = 0; nt < 4; nt++) {
                    int col = bn + wn * 32 + nt * 8 + t * 2;
                    float2 v;
                    v.x = acc[mt][nt][half * 2 + 0];
                    v.y = acc[mt][nt][half * 2 + 1];
                    if (bias) {
                        float2 b2v = *(const float2*)(bias + col);
                        v.x += b2v.x; v.y += b2v.y;
                    }
                    if (rp) {
                        float2 r2v = *(const float2*)(rp + col);
                        v.x += r2v.x; v.y += r2v.y;
                    }
                    *(float2*)(cp + col) = v;
                }
            }
        }
    } else if (emode == 1) {
        #pragma unroll
        for (int mt = 0; mt < 4; mt++) {
            #pragma unroll
            for (int half = 0; half < 2; half++) {
                int row = bm + wm * 64 + mt * 16 + g + half * 8;
                #pragma unroll
                for (int nt = 0; nt < 4; nt++) {
                    int gcol = bn + wn * 32 + nt * 8 + t * 2;
                    int j = gcol >> 1;
                    float val = acc[mt][nt][half * 2 + 0] + bias[j];
                    float gt  = acc[mt][nt][half * 2 + 1] + bias[HALF + j];
                    float s = gt / (1.0f + __expf(-gt));
                    Csp[(size_t)row * HALF + j] = __float2half_rn(s * val);
                }
            }
        }
    } else {
        #pragma unroll
        for (int mt = 0; mt < 4; mt++) {
            #pragma unroll
            for (int half = 0; half < 2; half++) {
                int row = bm + wm * 64 + mt * 16 + g + half * 8;
                int bq = row >> 11, t2 = row & (TT - 1);
                #pragma unroll
                for (int nt = 0; nt < 4; nt++) {
                    int col = bn + wn * 32 + nt * 8 + t * 2;
                    float vx = acc[mt][nt][half * 2 + 0];
                    float vy = acc[mt][nt][half * 2 + 1];
                    if (col < DD) {
                        *(uint32_t*)(Csp + (size_t)row * DD + col) =
                            packh(__float2half_rn(vx * SCL), __float2half_rn(vy * SCL));
                    } else if (col < 2 * DD) {
                        int c = col - DD; int h2 = c >> 6, hs = c & 63;
                        *(uint32_t*)(Kout + (((size_t)(bq * HH + h2) * TT + t2) << 6) + hs) =
                            packh(__float2half_rn(vx), __float2half_rn(vy));
                    } else {
                        int c = col - 2 * DD; int h2 = c >> 6, hs = c & 63;
                        size_t a0 = ((size_t)(bq * HH + h2) * 64 + hs) * TT + t2;
                        Vout[a0]      = __float2half_rn(vx);
                        Vout[a0 + TT] = __float2half_rn(vy);
                    }
                }
            }
        }
    }
}

// ---------------- tensor-core causal flash attention (fp16) -------------------
// smem: Q 128x72 fp16 (18432) | 3-stage ring x [K(9216) V(9216)]
#define ATT_STG 18432
#define ATT_SMEM (18432 + 3*ATT_STG)   // 73728

__global__ void __launch_bounds__(256, 2) attn_tc(
    const __half* __restrict__ Qb, const __half* __restrict__ KBi,
    const __half* __restrict__ VBi, __half* __restrict__ ATB)
{
    extern __shared__ char sm[];
    uint32_t sbase = smem_u32(sm);
    int tid = threadIdx.x, lane = tid & 31, wid = tid >> 5;
    int qt = (int)(gridDim.x - 1 - blockIdx.x);
    int bh = blockIdx.y, b = bh / HH, hh = bh % HH;
    int q0 = qt * 128;
    int nkt = 2 * qt + 2;

    int a_r = lane & 15, a_c = (lane & 16) ? 8 : 0;
    int b_r = ((lane >> 4) << 3) + (lane & 7), b_c = lane & 8;
    int g = lane >> 2, tq = lane & 3;
    const uint32_t ONES = 0x3C003C00u;   // fp16 1.0 x2 (all-ones B fragment)

    auto ldkv = [&](int kt, int stg) {
        uint32_t sb2 = sbase + 18432 + stg * ATT_STG;
        size_t kbase = ((size_t)bh * TT + kt * 64) * HS;
        size_t vbase = (size_t)bh * HS * TT + kt * 64;
        #pragma unroll
        for (int i = 0; i < 4; i++) {
            int ch = i * 256 + tid;
            int tile = ch >> 9;
            int r = (ch >> 3) & 63, cc = ch & 7;
            uint32_t dst = sb2 + tile * 9216 + r * 144 + cc * 16;
            const __half* src = (tile == 0)
                ? KBi + kbase + r * 64 + cc * 8
                : VBi + vbase + (size_t)r * TT + cc * 8;
            CPASYNC(dst, src);
        }
    };

    // prologue: Q (own group), then first two K/V stages
    #pragma unroll
    for (int i = 0; i < 4; i++) {
        int p = i * 256 + tid;
        int row = p >> 3, cc = p & 7;
        CPASYNC(sbase + (uint32_t)(row * 144 + cc * 16),
                Qb + (size_t)(b * TT + q0 + row) * DD + hh * HS + cc * 8);
    }
    CPCOMMIT();
    ldkv(0, 0); CPCOMMIT();
    ldkv(1, 1); CPCOMMIT();

    float oacc[8][4];
    #pragma unroll
    for (int n = 0; n < 8; n++)
        #pragma unroll
        for (int j = 0; j < 4; j++) oacc[n][j] = 0.f;
    float lacc[4] = {0.f, 0.f, 0.f, 0.f};   // row-sum accumulator via ones-MMA

    for (int kt = 0; kt < nkt; kt++) {
        if (kt + 1 < nkt) { CPWAIT(1); } else { CPWAIT(0); }
        __syncthreads();
        if (kt + 2 < nkt) { ldkv(kt + 2, (kt + 2) % 3); CPCOMMIT(); }

        uint32_t KHb = sbase + 18432 + (kt % 3) * ATT_STG;
        uint32_t VHb = KHb + 9216;

        float sacc[8][4];
        #pragma unroll
        for (int n = 0; n < 8; n++)
            #pragma unroll
            for (int j = 0; j < 4; j++) sacc[n][j] = 0.f;

        #pragma unroll
        for (int ks = 0; ks < 4; ks++) {
            uint32_t qh[4];
            uint32_t qa = sbase + (uint32_t)(((wid * 16 + a_r) * 72 + ks * 16 + a_c) * 2);
            LDSM4(qh, qa);
            #pragma unroll
            for (int nt2 = 0; nt2 < 4; nt2++) {
                uint32_t kf[4];
                uint32_t ka = (uint32_t)(((nt2 * 16 + b_r) * 72 + ks * 16 + b_c) * 2);
                LDSM4(kf, KHb + ka);
                MMA16816(sacc[2*nt2],     qh, kf[0], kf[1]);
                MMA16816(sacc[2*nt2 + 1], qh, kf[2], kf[3]);
            }
        }

        // softmax numerators — mask only on the 2 diagonal tiles
        if (kt >= 2 * qt) {
            int r0 = q0 + wid * 16 + g, r1 = r0 + 8;
            int cb = kt * 64 + tq * 2;
            #pragma unroll
            for (int n = 0; n < 8; n++) {
                #pragma unroll
                for (int j = 0; j < 4; j++) {
                    int c = cb + n * 8 + (j & 1);
                    int r = (j < 2) ? r0 : r1;
                    sacc[n][j] = (c <= r) ? __expf(sacc[n][j]) : 0.f;
                }
            }
        } else {
            #pragma unroll
            for (int n = 0; n < 8; n++) {
                #pragma unroll
                for (int j = 0; j < 4; j++)
                    sacc[n][j] = __expf(sacc[n][j]);
            }
        }

        #pragma unroll
        for (int pk = 0; pk < 4; pk++) {
            uint32_t pa[4];
            pa[0] = packh(__float2half_rn(sacc[2*pk][0]),   __float2half_rn(sacc[2*pk][1]));
            pa[1] = packh(__float2half_rn(sacc[2*pk][2]),   __float2half_rn(sacc[2*pk][3]));
            pa[2] = packh(__float2half_rn(sacc[2*pk+1][0]), __float2half_rn(sacc[2*pk+1][1]));
            pa[3] = packh(__float2half_rn(sacc[2*pk+1][2]), __float2half_rn(sacc[2*pk+1][3]));
            // row sums of P (exact: same rounded P the PV MMAs consume)
            MMA16816(lacc, pa, ONES, ONES);
            #pragma unroll
            for (int nt2 = 0; nt2 < 4; nt2++) {
                uint32_t vf[4];
                uint32_t va = (uint32_t)(((nt2 * 16 + b_r) * 72 + pk * 16 + b_c) * 2);
                LDSM4(vf, VHb + va);
                MMA16816(oacc[2*nt2],     pa, vf[0], vf[1]);
                MMA16816(oacc[2*nt2 + 1], pa, vf[2], vf[3]);
            }
        }
    }

    float inv0 = 1.0f / lacc[0], inv1 = 1.0f / lacc[2];

    size_t rg0 = (size_t)(b * TT + q0 + wid * 16 + g);
    size_t rg1 = rg0 + 8;
    int lc = hh * HS + tq * 2;
    #pragma unroll
    for (int n = 0; n < 8; n++) {
        *(uint32_t*)(ATB + rg0 * DD + lc + n * 8) =
            packh(__float2half_rn(oacc[n][0] * inv0), __float2half_rn(oacc[n][1] * inv0));
        *(uint32_t*)(ATB + rg1 * DD + lc + n * 8) =
            packh(__float2half_rn(oacc[n][2] * inv1), __float2half_rn(oacc[n][3] * inv1));
    }
}

// ---------------- RMSNorm -> fp16 ---------------------------------------------
__global__ void __launch_bounds__(256) rmsnorm_h(
    const float* __restrict__ x, const float* __restrict__ gw,
    __half* __restrict__ o)
{
    int row = blockIdx.x;
    const float* xr = x + (size_t)row * DD;
    int tid = threadIdx.x;
    float ss = 0.f;
    for (int i = tid; i < DD; i += 256) { float v = xr[i]; ss += v * v; }
    #pragma unroll
    for (int o2 = 16; o2 > 0; o2 >>= 1) ss += __shfl_xor_sync(0xffffffffu, ss, o2);
    __shared__ float red[8];
    if ((tid & 31) == 0) red[tid >> 5] = ss;
    __syncthreads();
    if (tid < 8) {
        float v = red[tid];
        #pragma unroll
        for (int o2 = 4; o2 > 0; o2 >>= 1) v += __shfl_xor_sync(0xffu, v, o2);
        if (tid == 0) red[0] = v;
    }
    __syncthreads();
    float rms = sqrtf(red[0] * (1.0f / DD));
    float inv = 1.0f / (rms + 1e-8f);
    for (int i = tid; i < DD; i += 256)
        o[(size_t)row * DD + i] = __float2half_rn(gw[i] * xr[i] * inv);
}

// ---------------- launch -----------------------------------------------------
extern "C" void kernel_launch(void* const* d_in, const int* in_sizes, int n_in,
                              void* d_out, int out_size)
{
    const float* x  = (const float*)d_in[0];
    const float* Wq = (const float*)d_in[1];
    const float* Wk = (const float*)d_in[2];
    const float* Wv = (const float*)d_in[3];
    const float* Wo = (const float*)d_in[4];
    const float* bo = (const float*)d_in[5];
    const float* W1 = (const float*)d_in[6];
    const float* b1 = (const float*)d_in[7];
    const float* W2 = (const float*)d_in[8];
    const float* b2 = (const float*)d_in[9];
    const float* g1 = (const float*)d_in[10];
    const float* g2 = (const float*)d_in[11];
    float* out = (float*)d_out;

    float *x1;
    __half *ah, *qh, *atb, *h2b, *swb, *kb, *vb, *bqkv, *bo_, *b1_, *b2_;
    cudaGetSymbolAddress((void**)&x1,  g_x1);
    cudaGetSymbolAddress((void**)&ah,  g_ah);
    cudaGetSymbolAddress((void**)&qh,  g_qh);
    cudaGetSymbolAddress((void**)&atb, g_atb);
    cudaGetSymbolAddress((void**)&h2b, g_h2b);
    cudaGetSymbolAddress((void**)&swb, g_swb);
    cudaGetSymbolAddress((void**)&kb,  g_kb);
    cudaGetSymbolAddress((void**)&vb,  g_vb);
    cudaGetSymbolAddress((void**)&bqkv, g_bqkv);
    cudaGetSymbolAddress((void**)&bo_,  g_bo);
    cudaGetSymbolAddress((void**)&b1_,  g_b1);
    cudaGetSymbolAddress((void**)&b2_,  g_b2);

    cudaFuncSetAttribute(gemm_mma, cudaFuncAttributeMaxDynamicSharedMemorySize, GEMM_SMEM);
    cudaFuncSetAttribute(attn_tc,  cudaFuncAttributeMaxDynamicSharedMemorySize, ATT_SMEM);

    // 0) coalesced weight prep (single launch)
    prep_tr<<<PREP_GRID, 256>>>(Wq, Wk, Wv, Wo, W1, W2, bqkv, bo_, b1_, b2_);

    // 1) ah = fp16(rmsnorm(x, g1))
    rmsnorm_h<<<NT, 256>>>(x, g1, ah);

    // 2) qkv GEMM: epilogue scatters Q (scaled fp16), K, V^T per-head directly
    gemm_mma<<<dim3(QKVN / 128, NT / 128), 256, GEMM_SMEM>>>(
        ah, bqkv, nullptr, nullptr, nullptr, qh, kb, vb, NT, QKVN, DD, 2);

    // 3) attention -> atb (fp16)
    attn_tc<<<dim3(TT / 128, BH), 256, ATT_SMEM>>>(qh, kb, vb, atb);

    // 4) x1 = x + atb @ Wo + bo
    gemm_mma<<<dim3(DD / 128, NT / 128), 256, GEMM_SMEM>>>(
        atb, bo_, bo, x, x1, nullptr, nullptr, nullptr, NT, DD, DD, 0);

    // 5) h2b = fp16(rmsnorm(x1, g2))
    rmsnorm_h<<<NT, 256>>>(x1, g2, h2b);

    // 6) swb = swiglu(h2b @ W1' + b1)  — fused epilogue, interleaved W1
    gemm_mma<<<dim3(FF / 128, NT / 128), 256, GEMM_SMEM>>>(
        h2b, b1_, b1, nullptr, nullptr, swb, nullptr, nullptr, NT, FF, DD, 1);

    // 7) out = x1 + swb @ W2 + b2
    gemm_mma<<<dim3(DD / 128, NT / 128), 256, GEMM_SMEM>>>(
        swb, b2_, b2, x1, out, nullptr, nullptr, nullptr, NT, DD, HALF, 0);
}

// round 10
// speedup vs baseline: 2.3708x; 1.0223x over previous
#include <cuda_runtime.h>
#include <cuda_fp16.h>
#include <cstdint>
#include <cstddef>

// Problem constants
#define BB 2
#define TT 2048
#define DD 768
#define HH 12
#define HS 64
#define FF 3072
#define HALF 1536
#define NT (BB*TT)       // 4096
#define QKVN 2304        // fused q|k|v output width
#define BH 24            // B*H
#define SCL 0.03608439182435161f   // 768^-0.5

// ---------------- scratch (device globals) -----------------------------------
__device__ float g_x1 [(size_t)NT*DD];
__device__ __half g_ah [(size_t)NT*DD];    // rmsnorm1 out
__device__ __half g_qh [(size_t)NT*DD];    // Q (pre-scaled), from QKV epilogue
__device__ __half g_atb[(size_t)NT*DD];    // attention out
__device__ __half g_h2b[(size_t)NT*DD];    // rmsnorm2 out
__device__ __half g_swb[(size_t)NT*HALF];  // swiglu out (from W1 epi)
__device__ __half g_kb [(size_t)BH*TT*HS]; // K [bh][t][64]
__device__ __half g_vb [(size_t)BH*TT*HS]; // V^T [bh][hs][T]
// split-K attention partials: 8 qt x 24 bh x 2 halves x 128 rows x 64 cols
__device__ float g_po [(size_t)8*24*2*128*64];
__device__ float g_pl [(size_t)8*24*2*128];
// fp16 weights, layout [N][K]
__device__ __half g_bqkv[(size_t)QKVN*DD];
__device__ __half g_bo  [(size_t)DD*DD];
__device__ __half g_b1  [(size_t)FF*DD];   // column-interleaved (val,gate)
__device__ __half g_b2  [(size_t)DD*HALF];

// ---------------- helpers ----------------------------------------------------
__device__ __forceinline__ uint32_t smem_u32(const void* p) {
    uint32_t a;
    asm("{ .reg .u64 t; cvta.to.shared.u64 t, %1; cvt.u32.u64 %0, t; }" : "=r"(a) : "l"(p));
    return a;
}
#define CPASYNC(d, s) asm volatile("cp.async.cg.shared.global [%0], [%1], 16;" :: "r"(d), "l"(s) : "memory")
#define CPCOMMIT()    asm volatile("cp.async.commit_group;" ::: "memory")
#define CPWAIT(n)     asm volatile("cp.async.wait_group %0;" :: "n"(n) : "memory")
#define LDSM4(r, a)                                                              \
    asm volatile("ldmatrix.sync.aligned.m8n8.x4.shared.b16 {%0,%1,%2,%3}, [%4];" \
        : "=r"((r)[0]), "=r"((r)[1]), "=r"((r)[2]), "=r"((r)[3]) : "r"(a))
#define MMA16816(c, a, b0, b1)                                                   \
    asm volatile("mma.sync.aligned.m16n8k16.row.col.f32.f16.f16.f32 "            \
        "{%0,%1,%2,%3}, {%4,%5,%6,%7}, {%8,%9}, {%0,%1,%2,%3};"                  \
        : "+f"((c)[0]), "+f"((c)[1]), "+f"((c)[2]), "+f"((c)[3])                 \
        : "r"((a)[0]), "r"((a)[1]), "r"((a)[2]), "r"((a)[3]), "r"(b0), "r"(b1))

__device__ __forceinline__ uint32_t packh(__half a, __half b) {
    return (uint32_t)__half_as_ushort(a) | ((uint32_t)__half_as_ushort(b) << 16);
}

// ---------------- coalesced weight prep: smem tile transpose -------------------
__global__ void __launch_bounds__(256) prep_tr(
    const float* __restrict__ Wq, const float* __restrict__ Wk,
    const float* __restrict__ Wv, const float* __restrict__ Wo,
    const float* __restrict__ W1, const float* __restrict__ W2,
    __half* __restrict__ bqkv, __half* __restrict__ bo,
    __half* __restrict__ b1,  __half* __restrict__ b2)
{
    __shared__ float ts[32][33];
    int bid = blockIdx.x;
    int tx = threadIdx.x & 31, ty = threadIdx.x >> 5;

    const float* W; __half* dst;
    int K, mode, srcLd, tn, tk;
    if (bid < 2304) {
        int m = bid / 576, lt = bid - m * 576;
        W = (m == 0) ? Wq : (m == 1) ? Wk : (m == 2) ? Wv : Wo;
        dst = (m < 3) ? bqkv + (size_t)m * 768 * 768 : bo;
        K = 768; mode = (m < 3) ? 1 : 0; srcLd = 768;
        tn = lt / 24; tk = lt - (lt / 24) * 24;
    } else if (bid < 4608) {
        int lt = bid - 2304;
        W = W1; dst = b1; K = 768; mode = 2; srcLd = 3072;
        tn = lt / 24; tk = lt - (lt / 24) * 24;
    } else {
        int lt = bid - 4608;
        W = W2; dst = b2; K = 1536; mode = 0; srcLd = 768;
        tn = lt / 48; tk = lt - (lt / 48) * 48;
    }
    int k0 = tk * 32, n0 = tn * 32;

    #pragma unroll
    for (int i = 0; i < 4; i++) {
        int kk = ty + i * 8;
        float v; int col;
        if (mode == 0) {
            v = W[(size_t)(k0 + kk) * srcLd + n0 + tx];
            col = tx;
        } else if (mode == 1) {
            v = W[(size_t)(n0 >> 6) * (768 * 64) + (size_t)(k0 + kk) * 64 + (n0 & 63) + tx];
            col = tx;
        } else {
            int j = tx & 15, grp = tx >> 4;
            v = W[(size_t)(k0 + kk) * 3072 + (grp ? HALF : 0) + (n0 >> 1) + j];
            col = 2 * j + grp;
        }
        ts[kk][col] = v;
    }
    __syncthreads();
    #pragma unroll
    for (int i = 0; i < 4; i++) {
        int nn = ty + i * 8;
        dst[(size_t)(n0 + nn) * K + k0 + tx] = __float2half_rn(ts[tx][nn]);
    }
}
#define PREP_GRID 5760

// ---------------- mma.sync fp16 GEMM ------------------------------------------
#define KB 64
#define PADE 72
#define TILEB (128*PADE*2)
#define STGB  (2*TILEB)
#define GEMM_SMEM (2*STGB)

__global__ void __launch_bounds__(256, 2) gemm_mma(
    const __half* __restrict__ Ap, const __half* __restrict__ Bp,
    const float* __restrict__ bias, const float* __restrict__ resid,
    float* __restrict__ C, __half* __restrict__ Csp,
    __half* __restrict__ Kout, __half* __restrict__ Vout,
    int M, int N, int K, int emode)
{
    extern __shared__ char sm[];
    int tid = threadIdx.x, lane = tid & 31, wid = tid >> 5;
    int wm = wid >> 2, wn = wid & 3;
    int bm = blockIdx.y * 128, bn = blockIdx.x * 128;
    uint32_t sbase = smem_u32(sm);

    float acc[4][4][4];
    #pragma unroll
    for (int i = 0; i < 4; i++)
        #pragma unroll
        for (int j = 0; j < 4; j++)
            #pragma unroll
            for (int q = 0; q < 4; q++) acc[i][j][q] = 0.f;

    int a_r = lane & 15, a_c = (lane & 16) ? 8 : 0;
    int b_r = ((lane >> 4) << 3) + (lane & 7), b_c = (lane & 8);
    const int KBn = K / KB;

    auto load_stage = [&](int kb, int stg) {
        #pragma unroll
        for (int t2 = 0; t2 < 2; t2++) {
            const __half* base = t2 ? Bp : Ap;
            int rowbase = t2 ? bn : bm;
            #pragma unroll
            for (int i = 0; i < 4; i++) {
                int c = i * 256 + tid;
                int row = c >> 3, cc = c & 7;
                uint32_t dst = sbase + stg * STGB + t2 * TILEB
                             + (uint32_t)(row * (PADE * 2) + cc * 16);
                const __half* src =
                    base + (size_t)(rowbase + row) * K + kb * KB + cc * 8;
                CPASYNC(dst, src);
            }
        }
    };

    load_stage(0, 0);
    CPCOMMIT();

    for (int kb = 0; kb < KBn; kb++) {
        CPWAIT(0);
        __syncthreads();
        if (kb + 1 < KBn) { load_stage(kb + 1, (kb + 1) & 1); CPCOMMIT(); }

        uint32_t sa = sbase + (kb & 1) * STGB;
        uint32_t aof = sa, bof = sa + TILEB;
        #pragma unroll
        for (int ks = 0; ks < KB; ks += 16) {
            uint32_t af[4][4], bf2[2][4];
            #pragma unroll
            for (int mt = 0; mt < 4; mt++) {
                uint32_t off = (uint32_t)(((wm * 64 + mt * 16 + a_r) * PADE + ks + a_c) * 2);
                LDSM4(af[mt], aof + off);
            }
            #pragma unroll
            for (int np = 0; np < 2; np++) {
                uint32_t off = (uint32_t)(((wn * 32 + np * 16 + b_r) * PADE + ks + b_c) * 2);
                LDSM4(bf2[np], bof + off);
            }
            #pragma unroll
            for (int mt = 0; mt < 4; mt++)
                #pragma unroll
                for (int nt = 0; nt < 4; nt++)
                    MMA16816(acc[mt][nt], af[mt],
                             bf2[nt >> 1][(nt & 1) * 2], bf2[nt >> 1][(nt & 1) * 2 + 1]);
        }
    }

    int g = lane >> 2, t = lane & 3;
    if (emode == 0) {
        #pragma unroll
        for (int mt = 0; mt < 4; mt++) {
            #pragma unroll
            for (int half = 0; half < 2; half++) {
                int row = bm + wm * 64 + mt * 16 + g + half * 8;
                float* cp = C + (size_t)row * N;
                const float* rp = resid ? (resid + (size_t)row * N) : nullptr;
                #pragma unroll
                for (int nt = 0; nt < 4; nt++) {
                    int col = bn + wn * 32 + nt * 8 + t * 2;
                    float2 v;
                    v.x = acc[mt][nt][half * 2 + 0];
                    v.y = acc[mt][nt][half * 2 + 1];
                    if (bias) {
                        float2 b2v = *(const float2*)(bias + col);
                        v.x += b2v.x; v.y += b2v.y;
                    }
                    if (rp) {
                        float2 r2v = *(const float2*)(rp + col);
                        v.x += r2v.x; v.y += r2v.y;
                    }
                    *(float2*)(cp + col) = v;
                }
            }
        }
    } else if (emode == 1) {
        #pragma unroll
        for (int mt = 0; mt < 4; mt++) {
            #pragma unroll
            for (int half = 0; half < 2; half++) {
                int row = bm + wm * 64 + mt * 16 + g + half * 8;
                #pragma unroll
                for (int nt = 0; nt < 4; nt++) {
                    int gcol = bn + wn * 32 + nt * 8 + t * 2;
                    int j = gcol >> 1;
                    float val = acc[mt][nt][half * 2 + 0] + bias[j];
                    float gt  = acc[mt][nt][half * 2 + 1] + bias[HALF + j];
                    float s = gt / (1.0f + __expf(-gt));
                    Csp[(size_t)row * HALF + j] = __float2half_rn(s * val);
                }
            }
        }
    } else {
        #pragma unroll
        for (int mt = 0; mt < 4; mt++) {
            #pragma unroll
            for (int half = 0; half < 2; half++) {
                int row = bm + wm * 64 + mt * 16 + g + half * 8;
                int bq = row >> 11, t2 = row & (TT - 1);
                #pragma unroll
                for (int nt = 0; nt < 4; nt++) {
                    int col = bn + wn * 32 + nt * 8 + t * 2;
                    float vx = acc[mt][nt][half * 2 + 0];
                    float vy = acc[mt][nt][half * 2 + 1];
                    if (col < DD) {
                        *(uint32_t*)(Csp + (size_t)row * DD + col) =
                            packh(__float2half_rn(vx * SCL), __float2half_rn(vy * SCL));
                    } else if (col < 2 * DD) {
                        int c = col - DD; int h2 = c >> 6, hs = c & 63;
                        *(uint32_t*)(Kout + (((size_t)(bq * HH + h2) * TT + t2) << 6) + hs) =
                            packh(__float2half_rn(vx), __float2half_rn(vy));
                    } else {
                        int c = col - 2 * DD; int h2 = c >> 6, hs = c & 63;
                        size_t a0 = ((size_t)(bq * HH + h2) * 64 + hs) * TT + t2;
                        Vout[a0]      = __float2half_rn(vx);
                        Vout[a0 + TT] = __float2half_rn(vy);
                    }
                }
            }
        }
    }
}

// ---------------- tensor-core causal flash attention (fp16, split-K) ----------
// 24 work units per bh, longest-first static schedule:
//  qt 0..7 unsplit; qt 8..15 split into two half-key-range CTAs.
//  Split CTAs write fp32 (o, l) partials; merge kernel combines additively
//  (valid because softmax is computed without running max: o,l sum linearly).
#define ATT_STG 18432
#define ATT_SMEM (18432 + 3*ATT_STG)   // 73728

__global__ void __launch_bounds__(256, 2) attn_tc(
    const __half* __restrict__ Qb, const __half* __restrict__ KBi,
    const __half* __restrict__ VBi, __half* __restrict__ ATB,
    float* __restrict__ Po, float* __restrict__ Pl)
{
    static const signed char UQT[24] = {7,15,15,14,14,6,13,13,12,12,5,11,
                                        11,10,10,4,9,9,8,8,3,2,1,0};
    static const signed char UHS[24] = {-1,0,1,0,1,-1,0,1,0,1,-1,0,
                                        1,0,1,-1,0,1,0,1,-1,-1,-1,-1};
    extern __shared__ char sm[];
    uint32_t sbase = smem_u32(sm);
    int tid = threadIdx.x, lane = tid & 31, wid = tid >> 5;
    int u = blockIdx.x;
    int qt = UQT[u], hsp = UHS[u];
    int bh = blockIdx.y, b = bh / HH, hh = bh % HH;
    int q0 = qt * 128;
    int kt0 = (hsp == 1) ? (qt + 1) : 0;
    int kt1 = (hsp == 0) ? (qt + 1) : (2 * qt + 2);
    int nloc = kt1 - kt0;

    int a_r = lane & 15, a_c = (lane & 16) ? 8 : 0;
    int b_r = ((lane >> 4) << 3) + (lane & 7), b_c = lane & 8;
    int g = lane >> 2, tq = lane & 3;
    const uint32_t ONES = 0x3C003C00u;

    auto ldkv = [&](int kt, int stg) {
        uint32_t sb2 = sbase + 18432 + stg * ATT_STG;
        size_t kbase = ((size_t)bh * TT + kt * 64) * HS;
        size_t vbase = (size_t)bh * HS * TT + kt * 64;
        #pragma unroll
        for (int i = 0; i < 4; i++) {
            int ch = i * 256 + tid;
            int tile = ch >> 9;
            int r = (ch >> 3) & 63, cc = ch & 7;
            uint32_t dst = sb2 + tile * 9216 + r * 144 + cc * 16;
            const __half* src = (tile == 0)
                ? KBi + kbase + r * 64 + cc * 8
                : VBi + vbase + (size_t)r * TT + cc * 8;
            CPASYNC(dst, src);
        }
    };

    // prologue: Q (own group), first two K/V stages (nloc >= 2 always)
    #pragma unroll
    for (int i = 0; i < 4; i++) {
        int p = i * 256 + tid;
        int row = p >> 3, cc = p & 7;
        CPASYNC(sbase + (uint32_t)(row * 144 + cc * 16),
                Qb + (size_t)(b * TT + q0 + row) * DD + hh * HS + cc * 8);
    }
    CPCOMMIT();
    ldkv(kt0, 0);     CPCOMMIT();
    ldkv(kt0 + 1, 1); CPCOMMIT();

    float oacc[8][4];
    #pragma unroll
    for (int n = 0; n < 8; n++)
        #pragma unroll
        for (int j = 0; j < 4; j++) oacc[n][j] = 0.f;
    float lacc[4] = {0.f, 0.f, 0.f, 0.f};

    for (int it = 0; it < nloc; it++) {
        if (it + 1 < nloc) { CPWAIT(1); } else { CPWAIT(0); }
        __syncthreads();
        if (it + 2 < nloc) { ldkv(kt0 + it + 2, (it + 2) % 3); CPCOMMIT(); }

        int kt = kt0 + it;
        uint32_t KHb = sbase + 18432 + (it % 3) * ATT_STG;
        uint32_t VHb = KHb + 9216;

        float sacc[8][4];
        #pragma unroll
        for (int n = 0; n < 8; n++)
            #pragma unroll
            for (int j = 0; j < 4; j++) sacc[n][j] = 0.f;

        #pragma unroll
        for (int ks = 0; ks < 4; ks++) {
            uint32_t qh[4];
            uint32_t qa = sbase + (uint32_t)(((wid * 16 + a_r) * 72 + ks * 16 + a_c) * 2);
            LDSM4(qh, qa);
            #pragma unroll
            for (int nt2 = 0; nt2 < 4; nt2++) {
                uint32_t kf[4];
                uint32_t ka = (uint32_t)(((nt2 * 16 + b_r) * 72 + ks * 16 + b_c) * 2);
                LDSM4(kf, KHb + ka);
                MMA16816(sacc[2*nt2],     qh, kf[0], kf[1]);
                MMA16816(sacc[2*nt2 + 1], qh, kf[2], kf[3]);
            }
        }

        if (kt >= 2 * qt) {        // diagonal tiles only
            int r0 = q0 + wid * 16 + g, r1 = r0 + 8;
            int cb = kt * 64 + tq * 2;
            #pragma unroll
            for (int n = 0; n < 8; n++) {
                #pragma unroll
                for (int j = 0; j < 4; j++) {
                    int c = cb + n * 8 + (j & 1);
                    int r = (j < 2) ? r0 : r1;
                    sacc[n][j] = (c <= r) ? __expf(sacc[n][j]) : 0.f;
                }
            }
        } else {
            #pragma unroll
            for (int n = 0; n < 8; n++)
                #pragma unroll
                for (int j = 0; j < 4; j++)
                    sacc[n][j] = __expf(sacc[n][j]);
        }

        #pragma unroll
        for (int pk = 0; pk < 4; pk++) {
            uint32_t pa[4];
            pa[0] = packh(__float2half_rn(sacc[2*pk][0]),   __float2half_rn(sacc[2*pk][1]));
            pa[1] = packh(__float2half_rn(sacc[2*pk][2]),   __float2half_rn(sacc[2*pk][3]));
            pa[2] = packh(__float2half_rn(sacc[2*pk+1][0]), __float2half_rn(sacc[2*pk+1][1]));
            pa[3] = packh(__float2half_rn(sacc[2*pk+1][2]), __float2half_rn(sacc[2*pk+1][3]));
            MMA16816(lacc, pa, ONES, ONES);
            #pragma unroll
            for (int nt2 = 0; nt2 < 4; nt2++) {
                uint32_t vf[4];
                uint32_t va = (uint32_t)(((nt2 * 16 + b_r) * 72 + pk * 16 + b_c) * 2);
                LDSM4(vf, VHb + va);
                MMA16816(oacc[2*nt2],     pa, vf[0], vf[1]);
                MMA16816(oacc[2*nt2 + 1], pa, vf[2], vf[3]);
            }
        }
    }

    if (hsp < 0) {
        // unsplit: normalize and write fp16 output directly
        float inv0 = 1.0f / lacc[0], inv1 = 1.0f / lacc[2];
        size_t rg0 = (size_t)(b * TT + q0 + wid * 16 + g);
        size_t rg1 = rg0 + 8;
        int lc = hh * HS + tq * 2;
        #pragma unroll
        for (int n = 0; n < 8; n++) {
            *(uint32_t*)(ATB + rg0 * DD + lc + n * 8) =
                packh(__float2half_rn(oacc[n][0] * inv0), __float2half_rn(oacc[n][1] * inv0));
            *(uint32_t*)(ATB + rg1 * DD + lc + n * 8) =
                packh(__float2half_rn(oacc[n][2] * inv1), __float2half_rn(oacc[n][3] * inv1));
        }
    } else {
        // split: write raw fp32 partials
        int u2 = ((qt - 8) * 24 + bh) * 2 + hsp;
        int r0 = wid * 16 + g;
        float* p0 = Po + ((size_t)u2 * 128 + r0) * 64 + tq * 2;
        float* p1 = Po + ((size_t)u2 * 128 + r0 + 8) * 64 + tq * 2;
        #pragma unroll
        for (int n = 0; n < 8; n++) {
            float2 v0; v0.x = oacc[n][0]; v0.y = oacc[n][1];
            float2 v1; v1.x = oacc[n][2]; v1.y = oacc[n][3];
            *(float2*)(p0 + n * 8) = v0;
            *(float2*)(p1 + n * 8) = v1;
        }
        if (tq == 0) {
            Pl[(size_t)u2 * 128 + r0]     = lacc[0];
            Pl[(size_t)u2 * 128 + r0 + 8] = lacc[2];
        }
    }
}

// ---------------- merge split-K attention partials -----------------------------
// idx over 8 qt x 24 bh x 128 rows x 32 col-pairs = 786432 threads
__global__ void __launch_bounds__(256) attn_merge(
    const float* __restrict__ Po, const float* __restrict__ Pl,
    __half* __restrict__ ATB)
{
    int idx = blockIdx.x * 256 + threadIdx.x;
    int cp = idx & 31;
    int t  = idx >> 5;
    int row = t & 127;
    int t2 = t >> 7;
    int bh = t2 % 24, qidx = t2 / 24;
    int qt = qidx + 8;
    int b = bh / HH, hh = bh % HH;

    size_t ub = ((size_t)(qidx * 24 + bh)) * 2;
    size_t o0 = (ub * 128 + row) * 64 + cp * 2;
    size_t o1 = ((ub + 1) * 128 + row) * 64 + cp * 2;
    float2 a = *(const float2*)(Po + o0);
    float2 c = *(const float2*)(Po + o1);
    float l = Pl[ub * 128 + row] + Pl[(ub + 1) * 128 + row];
    float inv = 1.0f / l;

    size_t gr = (size_t)(b * TT + qt * 128 + row);
    *(uint32_t*)(ATB + gr * DD + hh * HS + cp * 2) =
        packh(__float2half_rn((a.x + c.x) * inv), __float2half_rn((a.y + c.y) * inv));
}

// ---------------- RMSNorm -> fp16 ---------------------------------------------
__global__ void __launch_bounds__(256) rmsnorm_h(
    const float* __restrict__ x, const float* __restrict__ gw,
    __half* __restrict__ o)
{
    int row = blockIdx.x;
    const float* xr = x + (size_t)row * DD;
    int tid = threadIdx.x;
    float ss = 0.f;
    for (int i = tid; i < DD; i += 256) { float v = xr[i]; ss += v * v; }
    #pragma unroll
    for (int o2 = 16; o2 > 0; o2 >>= 1) ss += __shfl_xor_sync(0xffffffffu, ss, o2);
    __shared__ float red[8];
    if ((tid & 31) == 0) red[tid >> 5] = ss;
    __syncthreads();
    if (tid < 8) {
        float v = red[tid];
        #pragma unroll
        for (int o2 = 4; o2 > 0; o2 >>= 1) v += __shfl_xor_sync(0xffu, v, o2);
        if (tid == 0) red[0] = v;
    }
    __syncthreads();
    float rms = sqrtf(red[0] * (1.0f / DD));
    float inv = 1.0f / (rms + 1e-8f);
    for (int i = tid; i < DD; i += 256)
        o[(size_t)row * DD + i] = __float2half_rn(gw[i] * xr[i] * inv);
}

// ---------------- launch -----------------------------------------------------
extern "C" void kernel_launch(void* const* d_in, const int* in_sizes, int n_in,
                              void* d_out, int out_size)
{
    const float* x  = (const float*)d_in[0];
    const float* Wq = (const float*)d_in[1];
    const float* Wk = (const float*)d_in[2];
    const float* Wv = (const float*)d_in[3];
    const float* Wo = (const float*)d_in[4];
    const float* bo = (const float*)d_in[5];
    const float* W1 = (const float*)d_in[6];
    const float* b1 = (const float*)d_in[7];
    const float* W2 = (const float*)d_in[8];
    const float* b2 = (const float*)d_in[9];
    const float* g1 = (const float*)d_in[10];
    const float* g2 = (const float*)d_in[11];
    float* out = (float*)d_out;

    float *x1, *po, *pl;
    __half *ah, *qh, *atb, *h2b, *swb, *kb, *vb, *bqkv, *bo_, *b1_, *b2_;
    cudaGetSymbolAddress((void**)&x1,  g_x1);
    cudaGetSymbolAddress((void**)&po,  g_po);
    cudaGetSymbolAddress((void**)&pl,  g_pl);
    cudaGetSymbolAddress((void**)&ah,  g_ah);
    cudaGetSymbolAddress((void**)&qh,  g_qh);
    cudaGetSymbolAddress((void**)&atb, g_atb);
    cudaGetSymbolAddress((void**)&h2b, g_h2b);
    cudaGetSymbolAddress((void**)&swb, g_swb);
    cudaGetSymbolAddress((void**)&kb,  g_kb);
    cudaGetSymbolAddress((void**)&vb,  g_vb);
    cudaGetSymbolAddress((void**)&bqkv, g_bqkv);
    cudaGetSymbolAddress((void**)&bo_,  g_bo);
    cudaGetSymbolAddress((void**)&b1_,  g_b1);
    cudaGetSymbolAddress((void**)&b2_,  g_b2);

    cudaFuncSetAttribute(gemm_mma, cudaFuncAttributeMaxDynamicSharedMemorySize, GEMM_SMEM);
    cudaFuncSetAttribute(attn_tc,  cudaFuncAttributeMaxDynamicSharedMemorySize, ATT_SMEM);

    // 0) coalesced weight prep (single launch)
    prep_tr<<<PREP_GRID, 256>>>(Wq, Wk, Wv, Wo, W1, W2, bqkv, bo_, b1_, b2_);

    // 1) ah = fp16(rmsnorm(x, g1))
    rmsnorm_h<<<NT, 256>>>(x, g1, ah);

    // 2) qkv GEMM: epilogue scatters Q (scaled fp16), K, V^T per-head directly
    gemm_mma<<<dim3(QKVN / 128, NT / 128), 256, GEMM_SMEM>>>(
        ah, bqkv, nullptr, nullptr, nullptr, qh, kb, vb, NT, QKVN, DD, 2);

    // 3) attention (split-K, 24 units/bh) -> atb + partials
    attn_tc<<<dim3(24, BH), 256, ATT_SMEM>>>(qh, kb, vb, atb, po, pl);

    // 4) merge split-K partials into atb
    attn_merge<<<3072, 256>>>(po, pl, atb);

    // 5) x1 = x + atb @ Wo + bo
    gemm_mma<<<dim3(DD / 128, NT / 128), 256, GEMM_SMEM>>>(
        atb, bo_, bo, x, x1, nullptr, nullptr, nullptr, NT, DD, DD, 0);

    // 6) h2b = fp16(rmsnorm(x1, g2))
    rmsnorm_h<<<NT, 256>>>(x1, g2, h2b);

    // 7) swb = swiglu(h2b @ W1' + b1)  — fused epilogue, interleaved W1
    gemm_mma<<<dim3(FF / 128, NT / 128), 256, GEMM_SMEM>>>(
        h2b, b1_, b1, nullptr, nullptr, swb, nullptr, nullptr, NT, FF, DD, 1);

    // 8) out = x1 + swb @ W2 + b2
    gemm_mma<<<dim3(DD / 128, NT / 128), 256, GEMM_SMEM>>>(
        swb, b2_, b2, x1, out, nullptr, nullptr, nullptr, NT, DD, HALF, 0);
}

// round 11
// speedup vs baseline: 2.5593x; 1.0795x over previous
#include <cuda_runtime.h>
#include <cuda_fp16.h>
#include <cstdint>
#include <cstddef>

// Problem constants
#define BB 2
#define TT 2048
#define DD 768
#define HH 12
#define HS 64
#define FF 3072
#define HALF 1536
#define NT (BB*TT)       // 4096
#define QKVN 2304        // fused q|k|v output width
#define BH 24            // B*H
#define SCL 0.03608439182435161f   // 768^-0.5

// ---------------- scratch (device globals) -----------------------------------
__device__ float g_x1 [(size_t)NT*DD];
__device__ __half g_ah [(size_t)NT*DD];    // rmsnorm1 out
__device__ __half g_qh [(size_t)NT*DD];    // Q (pre-scaled), from QKV epilogue
__device__ __half g_atb[(size_t)NT*DD];    // attention out
__device__ __half g_h2b[(size_t)NT*DD];    // rmsnorm2 out
__device__ __half g_swb[(size_t)NT*HALF];  // swiglu out (from W1 epi)
__device__ __half g_kb [(size_t)BH*TT*HS]; // K [bh][t][64]
__device__ __half g_vb [(size_t)BH*TT*HS]; // V^T [bh][hs][T]
// split-K attention partials
__device__ float g_po [(size_t)8*24*2*128*64];
__device__ float g_pl [(size_t)8*24*2*128];
// fp16 weights, layout [N][K]
__device__ __half g_bqkv[(size_t)QKVN*DD];
__device__ __half g_bo  [(size_t)DD*DD];
__device__ __half g_b1  [(size_t)FF*DD];   // column-interleaved (val,gate)
__device__ __half g_b2  [(size_t)DD*HALF];

// ---------------- helpers ----------------------------------------------------
__device__ __forceinline__ uint32_t smem_u32(const void* p) {
    uint32_t a;
    asm("{ .reg .u64 t; cvta.to.shared.u64 t, %1; cvt.u32.u64 %0, t; }" : "=r"(a) : "l"(p));
    return a;
}
#define CPASYNC(d, s) asm volatile("cp.async.cg.shared.global [%0], [%1], 16;" :: "r"(d), "l"(s) : "memory")
#define CPCOMMIT()    asm volatile("cp.async.commit_group;" ::: "memory")
#define CPWAIT(n)     asm volatile("cp.async.wait_group %0;" :: "n"(n) : "memory")
#define LDSM4(r, a)                                                              \
    asm volatile("ldmatrix.sync.aligned.m8n8.x4.shared.b16 {%0,%1,%2,%3}, [%4];" \
        : "=r"((r)[0]), "=r"((r)[1]), "=r"((r)[2]), "=r"((r)[3]) : "r"(a))
#define MMA16816(c, a, b0, b1)                                                   \
    asm volatile("mma.sync.aligned.m16n8k16.row.col.f32.f16.f16.f32 "            \
        "{%0,%1,%2,%3}, {%4,%5,%6,%7}, {%8,%9}, {%0,%1,%2,%3};"                  \
        : "+f"((c)[0]), "+f"((c)[1]), "+f"((c)[2]), "+f"((c)[3])                 \
        : "r"((a)[0]), "r"((a)[1]), "r"((a)[2]), "r"((a)[3]), "r"(b0), "r"(b1))

__device__ __forceinline__ uint32_t packh(__half a, __half b) {
    return (uint32_t)__half_as_ushort(a) | ((uint32_t)__half_as_ushort(b) << 16);
}

// ---------------- coalesced weight prep: smem tile transpose -------------------
__global__ void __launch_bounds__(256) prep_tr(
    const float* __restrict__ Wq, const float* __restrict__ Wk,
    const float* __restrict__ Wv, const float* __restrict__ Wo,
    const float* __restrict__ W1, const float* __restrict__ W2,
    __half* __restrict__ bqkv, __half* __restrict__ bo,
    __half* __restrict__ b1,  __half* __restrict__ b2)
{
    __shared__ float ts[32][33];
    int bid = blockIdx.x;
    int tx = threadIdx.x & 31, ty = threadIdx.x >> 5;

    const float* W; __half* dst;
    int K, mode, srcLd, tn, tk;
    if (bid < 2304) {
        int m = bid / 576, lt = bid - m * 576;
        W = (m == 0) ? Wq : (m == 1) ? Wk : (m == 2) ? Wv : Wo;
        dst = (m < 3) ? bqkv + (size_t)m * 768 * 768 : bo;
        K = 768; mode = (m < 3) ? 1 : 0; srcLd = 768;
        tn = lt / 24; tk = lt - (lt / 24) * 24;
    } else if (bid < 4608) {
        int lt = bid - 2304;
        W = W1; dst = b1; K = 768; mode = 2; srcLd = 3072;
        tn = lt / 24; tk = lt - (lt / 24) * 24;
    } else {
        int lt = bid - 4608;
        W = W2; dst = b2; K = 1536; mode = 0; srcLd = 768;
        tn = lt / 48; tk = lt - (lt / 48) * 48;
    }
    int k0 = tk * 32, n0 = tn * 32;

    #pragma unroll
    for (int i = 0; i < 4; i++) {
        int kk = ty + i * 8;
        float v; int col;
        if (mode == 0) {
            v = W[(size_t)(k0 + kk) * srcLd + n0 + tx];
            col = tx;
        } else if (mode == 1) {
            v = W[(size_t)(n0 >> 6) * (768 * 64) + (size_t)(k0 + kk) * 64 + (n0 & 63) + tx];
            col = tx;
        } else {
            int j = tx & 15, grp = tx >> 4;
            v = W[(size_t)(k0 + kk) * 3072 + (grp ? HALF : 0) + (n0 >> 1) + j];
            col = 2 * j + grp;
        }
        ts[kk][col] = v;
    }
    __syncthreads();
    #pragma unroll
    for (int i = 0; i < 4; i++) {
        int nn = ty + i * 8;
        dst[(size_t)(n0 + nn) * K + k0 + tx] = __float2half_rn(ts[tx][nn]);
    }
}
#define PREP_GRID 5760

// ---------------- mma.sync fp16 GEMM ------------------------------------------
// CTA 128x64, 128 threads (2x2 warps, warp tile 64x32), K-block 64,
// 2-stage cp.async, one sync per k-block, 4 CTAs/SM.
// emode 0: C = acc + bias + resid (fp32); 1: swiglu -> Csp; 2: QKV scatter
#define KB 64
#define PADE 72
#define ATILE (128*PADE*2)       // 18432
#define BTILE (64*PADE*2)        // 9216
#define STGB  (ATILE+BTILE)      // 27648
#define GEMM_SMEM (2*STGB)       // 55296

__global__ void __launch_bounds__(128, 4) gemm_mma(
    const __half* __restrict__ Ap, const __half* __restrict__ Bp,
    const float* __restrict__ bias, const float* __restrict__ resid,
    float* __restrict__ C, __half* __restrict__ Csp,
    __half* __restrict__ Kout, __half* __restrict__ Vout,
    int M, int N, int K, int emode)
{
    extern __shared__ char sm[];
    int tid = threadIdx.x, lane = tid & 31, wid = tid >> 5;
    int wm = wid >> 1, wn = wid & 1;
    int bm = blockIdx.y * 128, bn = blockIdx.x * 64;
    uint32_t sbase = smem_u32(sm);

    float acc[4][4][4];
    #pragma unroll
    for (int i = 0; i < 4; i++)
        #pragma unroll
        for (int j = 0; j < 4; j++)
            #pragma unroll
            for (int q = 0; q < 4; q++) acc[i][j][q] = 0.f;

    int a_r = lane & 15, a_c = (lane & 16) ? 8 : 0;
    int b_r = ((lane >> 4) << 3) + (lane & 7), b_c = (lane & 8);
    const int KBn = K / KB;

    // stage loader: 12 cp.async per thread; i<8 -> A rows, i>=8 -> B rows
    auto load_stage = [&](int kb, int stg) {
        #pragma unroll
        for (int i = 0; i < 12; i++) {
            int c = i * 128 + tid;            // 0..1535
            int row = c >> 3, cc = c & 7;
            uint32_t dst;
            const __half* src;
            if (i < 8) {
                dst = sbase + stg * STGB + (uint32_t)(row * (PADE * 2) + cc * 16);
                src = Ap + (size_t)(bm + row) * K + kb * KB + cc * 8;
            } else {
                int r2 = row - 128;
                dst = sbase + stg * STGB + ATILE + (uint32_t)(r2 * (PADE * 2) + cc * 16);
                src = Bp + (size_t)(bn + r2) * K + kb * KB + cc * 8;
            }
            CPASYNC(dst, src);
        }
    };

    load_stage(0, 0);
    CPCOMMIT();

    for (int kb = 0; kb < KBn; kb++) {
        CPWAIT(0);
        __syncthreads();
        if (kb + 1 < KBn) { load_stage(kb + 1, (kb + 1) & 1); CPCOMMIT(); }

        uint32_t sa = sbase + (kb & 1) * STGB;
        uint32_t aof = sa, bof = sa + ATILE;
        #pragma unroll
        for (int ks = 0; ks < KB; ks += 16) {
            uint32_t af[4][4], bf2[2][4];
            #pragma unroll
            for (int mt = 0; mt < 4; mt++) {
                uint32_t off = (uint32_t)(((wm * 64 + mt * 16 + a_r) * PADE + ks + a_c) * 2);
                LDSM4(af[mt], aof + off);
            }
            #pragma unroll
            for (int np = 0; np < 2; np++) {
                uint32_t off = (uint32_t)(((wn * 32 + np * 16 + b_r) * PADE + ks + b_c) * 2);
                LDSM4(bf2[np], bof + off);
            }
            #pragma unroll
            for (int mt = 0; mt < 4; mt++)
                #pragma unroll
                for (int nt = 0; nt < 4; nt++)
                    MMA16816(acc[mt][nt], af[mt],
                             bf2[nt >> 1][(nt & 1) * 2], bf2[nt >> 1][(nt & 1) * 2 + 1]);
        }
    }

    int g = lane >> 2, t = lane & 3;
    if (emode == 0) {
        #pragma unroll
        for (int mt = 0; mt < 4; mt++) {
            #pragma unroll
            for (int half = 0; half < 2; half++) {
                int row = bm + wm * 64 + mt * 16 + g + half * 8;
                float* cp = C + (size_t)row * N;
                const float* rp = resid ? (resid + (size_t)row * N) : nullptr;
                #pragma unroll
                for (int nt = 0; nt < 4; nt++) {
                    int col = bn + wn * 32 + nt * 8 + t * 2;
                    float2 v;
                    v.x = acc[mt][nt][half * 2 + 0];
                    v.y = acc[mt][nt][half * 2 + 1];
                    if (bias) {
                        float2 b2v = *(const float2*)(bias + col);
                        v.x += b2v.x; v.y += b2v.y;
                    }
                    if (rp) {
                        float2 r2v = *(const float2*)(rp + col);
                        v.x += r2v.x; v.y += r2v.y;
                    }
                    *(float2*)(cp + col) = v;
                }
            }
        }
    } else if (emode == 1) {
        #pragma unroll
        for (int mt = 0; mt < 4; mt++) {
            #pragma unroll
            for (int half = 0; half < 2; half++) {
                int row = bm + wm * 64 + mt * 16 + g + half * 8;
                #pragma unroll
                for (int nt = 0; nt < 4; nt++) {
                    int gcol = bn + wn * 32 + nt * 8 + t * 2;
                    int j = gcol >> 1;
                    float val = acc[mt][nt][half * 2 + 0] + bias[j];
                    float gt  = acc[mt][nt][half * 2 + 1] + bias[HALF + j];
                    float s = gt / (1.0f + __expf(-gt));
                    Csp[(size_t)row * HALF + j] = __float2half_rn(s * val);
                }
            }
        }
    } else {
        #pragma unroll
        for (int mt = 0; mt < 4; mt++) {
            #pragma unroll
            for (int half = 0; half < 2; half++) {
                int row = bm + wm * 64 + mt * 16 + g + half * 8;
                int bq = row >> 11, t2 = row & (TT - 1);
                #pragma unroll
                for (int nt = 0; nt < 4; nt++) {
                    int col = bn + wn * 32 + nt * 8 + t * 2;
                    float vx = acc[mt][nt][half * 2 + 0];
                    float vy = acc[mt][nt][half * 2 + 1];
                    if (col < DD) {
                        *(uint32_t*)(Csp + (size_t)row * DD + col) =
                            packh(__float2half_rn(vx * SCL), __float2half_rn(vy * SCL));
                    } else if (col < 2 * DD) {
                        int c = col - DD; int h2 = c >> 6, hs = c & 63;
                        *(uint32_t*)(Kout + (((size_t)(bq * HH + h2) * TT + t2) << 6) + hs) =
                            packh(__float2half_rn(vx), __float2half_rn(vy));
                    } else {
                        int c = col - 2 * DD; int h2 = c >> 6, hs = c & 63;
                        size_t a0 = ((size_t)(bq * HH + h2) * 64 + hs) * TT + t2;
                        Vout[a0]      = __float2half_rn(vx);
                        Vout[a0 + TT] = __float2half_rn(vy);
                    }
                }
            }
        }
    }
}

// ---------------- tensor-core causal flash attention (fp16, split-K) ----------
#define ATT_STG 18432
#define ATT_SMEM (18432 + 3*ATT_STG)   // 73728

__global__ void __launch_bounds__(256, 2) attn_tc(
    const __half* __restrict__ Qb, const __half* __restrict__ KBi,
    const __half* __restrict__ VBi, __half* __restrict__ ATB,
    float* __restrict__ Po, float* __restrict__ Pl)
{
    static const signed char UQT[24] = {7,15,15,14,14,6,13,13,12,12,5,11,
                                        11,10,10,4,9,9,8,8,3,2,1,0};
    static const signed char UHS[24] = {-1,0,1,0,1,-1,0,1,0,1,-1,0,
                                        1,0,1,-1,0,1,0,1,-1,-1,-1,-1};
    extern __shared__ char sm[];
    uint32_t sbase = smem_u32(sm);
    int tid = threadIdx.x, lane = tid & 31, wid = tid >> 5;
    int u = blockIdx.x;
    int qt = UQT[u], hsp = UHS[u];
    int bh = blockIdx.y, b = bh / HH, hh = bh % HH;
    int q0 = qt * 128;
    int kt0 = (hsp == 1) ? (qt + 1) : 0;
    int kt1 = (hsp == 0) ? (qt + 1) : (2 * qt + 2);
    int nloc = kt1 - kt0;

    int a_r = lane & 15, a_c = (lane & 16) ? 8 : 0;
    int b_r = ((lane >> 4) << 3) + (lane & 7), b_c = lane & 8;
    int g = lane >> 2, tq = lane & 3;
    const uint32_t ONES = 0x3C003C00u;

    auto ldkv = [&](int kt, int stg) {
        uint32_t sb2 = sbase + 18432 + stg * ATT_STG;
        size_t kbase = ((size_t)bh * TT + kt * 64) * HS;
        size_t vbase = (size_t)bh * HS * TT + kt * 64;
        #pragma unroll
        for (int i = 0; i < 4; i++) {
            int ch = i * 256 + tid;
            int tile = ch >> 9;
            int r = (ch >> 3) & 63, cc = ch & 7;
            uint32_t dst = sb2 + tile * 9216 + r * 144 + cc * 16;
            const __half* src = (tile == 0)
                ? KBi + kbase + r * 64 + cc * 8
                : VBi + vbase + (size_t)r * TT + cc * 8;
            CPASYNC(dst, src);
        }
    };

    #pragma unroll
    for (int i = 0; i < 4; i++) {
        int p = i * 256 + tid;
        int row = p >> 3, cc = p & 7;
        CPASYNC(sbase + (uint32_t)(row * 144 + cc * 16),
                Qb + (size_t)(b * TT + q0 + row) * DD + hh * HS + cc * 8);
    }
    CPCOMMIT();
    ldkv(kt0, 0);     CPCOMMIT();
    ldkv(kt0 + 1, 1); CPCOMMIT();

    float oacc[8][4];
    #pragma unroll
    for (int n = 0; n < 8; n++)
        #pragma unroll
        for (int j = 0; j < 4; j++) oacc[n][j] = 0.f;
    float lacc[4] = {0.f, 0.f, 0.f, 0.f};

    for (int it = 0; it < nloc; it++) {
        if (it + 1 < nloc) { CPWAIT(1); } else { CPWAIT(0); }
        __syncthreads();
        if (it + 2 < nloc) { ldkv(kt0 + it + 2, (it + 2) % 3); CPCOMMIT(); }

        int kt = kt0 + it;
        uint32_t KHb = sbase + 18432 + (it % 3) * ATT_STG;
        uint32_t VHb = KHb + 9216;

        float sacc[8][4];
        #pragma unroll
        for (int n = 0; n < 8; n++)
            #pragma unroll
            for (int j = 0; j < 4; j++) sacc[n][j] = 0.f;

        #pragma unroll
        for (int ks = 0; ks < 4; ks++) {
            uint32_t qh[4];
            uint32_t qa = sbase + (uint32_t)(((wid * 16 + a_r) * 72 + ks * 16 + a_c) * 2);
            LDSM4(qh, qa);
            #pragma unroll
            for (int nt2 = 0; nt2 < 4; nt2++) {
                uint32_t kf[4];
                uint32_t ka = (uint32_t)(((nt2 * 16 + b_r) * 72 + ks * 16 + b_c) * 2);
                LDSM4(kf, KHb + ka);
                MMA16816(sacc[2*nt2],     qh, kf[0], kf[1]);
                MMA16816(sacc[2*nt2 + 1], qh, kf[2], kf[3]);
            }
        }

        if (kt >= 2 * qt) {
            int r0 = q0 + wid * 16 + g, r1 = r0 + 8;
            int cb = kt * 64 + tq * 2;
            #pragma unroll
            for (int n = 0; n < 8; n++) {
                #pragma unroll
                for (int j = 0; j < 4; j++) {
                    int c = cb + n * 8 + (j & 1);
                    int r = (j < 2) ? r0 : r1;
                    sacc[n][j] = (c <= r) ? __expf(sacc[n][j]) : 0.f;
                }
            }
        } else {
            #pragma unroll
            for (int n = 0; n < 8; n++)
                #pragma unroll
                for (int j = 0; j < 4; j++)
                    sacc[n][j] = __expf(sacc[n][j]);
        }

        #pragma unroll
        for (int pk = 0; pk < 4; pk++) {
            uint32_t pa[4];
            pa[0] = packh(__float2half_rn(sacc[2*pk][0]),   __float2half_rn(sacc[2*pk][1]));
            pa[1] = packh(__float2half_rn(sacc[2*pk][2]),   __float2half_rn(sacc[2*pk][3]));
            pa[2] = packh(__float2half_rn(sacc[2*pk+1][0]), __float2half_rn(sacc[2*pk+1][1]));
            pa[3] = packh(__float2half_rn(sacc[2*pk+1][2]), __float2half_rn(sacc[2*pk+1][3]));
            MMA16816(lacc, pa, ONES, ONES);
            #pragma unroll
            for (int nt2 = 0; nt2 < 4; nt2++) {
                uint32_t vf[4];
                uint32_t va = (uint32_t)(((nt2 * 16 + b_r) * 72 + pk * 16 + b_c) * 2);
                LDSM4(vf, VHb + va);
                MMA16816(oacc[2*nt2],     pa, vf[0], vf[1]);
                MMA16816(oacc[2*nt2 + 1], pa, vf[2], vf[3]);
            }
        }
    }

    if (hsp < 0) {
        float inv0 = 1.0f / lacc[0], inv1 = 1.0f / lacc[2];
        size_t rg0 = (size_t)(b * TT + q0 + wid * 16 + g);
        size_t rg1 = rg0 + 8;
        int lc = hh * HS + tq * 2;
        #pragma unroll
        for (int n = 0; n < 8; n++) {
            *(uint32_t*)(ATB + rg0 * DD + lc + n * 8) =
                packh(__float2half_rn(oacc[n][0] * inv0), __float2half_rn(oacc[n][1] * inv0));
            *(uint32_t*)(ATB + rg1 * DD + lc + n * 8) =
                packh(__float2half_rn(oacc[n][2] * inv1), __float2half_rn(oacc[n][3] * inv1));
        }
    } else {
        int u2 = ((qt - 8) * 24 + bh) * 2 + hsp;
        int r0 = wid * 16 + g;
        float* p0 = Po + ((size_t)u2 * 128 + r0) * 64 + tq * 2;
        float* p1 = Po + ((size_t)u2 * 128 + r0 + 8) * 64 + tq * 2;
        #pragma unroll
        for (int n = 0; n < 8; n++) {
            float2 v0; v0.x = oacc[n][0]; v0.y = oacc[n][1];
            float2 v1; v1.x = oacc[n][2]; v1.y = oacc[n][3];
            *(float2*)(p0 + n * 8) = v0;
            *(float2*)(p1 + n * 8) = v1;
        }
        if (tq == 0) {
            Pl[(size_t)u2 * 128 + r0]     = lacc[0];
            Pl[(size_t)u2 * 128 + r0 + 8] = lacc[2];
        }
    }
}

// ---------------- merge split-K attention partials -----------------------------
__global__ void __launch_bounds__(256) attn_merge(
    const float* __restrict__ Po, const float* __restrict__ Pl,
    __half* __restrict__ ATB)
{
    int idx = blockIdx.x * 256 + threadIdx.x;
    int cp = idx & 31;
    int t  = idx >> 5;
    int row = t & 127;
    int t2 = t >> 7;
    int bh = t2 % 24, qidx = t2 / 24;
    int qt = qidx + 8;
    int b = bh / HH, hh = bh % HH;

    size_t ub = ((size_t)(qidx * 24 + bh)) * 2;
    size_t o0 = (ub * 128 + row) * 64 + cp * 2;
    size_t o1 = ((ub + 1) * 128 + row) * 64 + cp * 2;
    float2 a = *(const float2*)(Po + o0);
    float2 c = *(const float2*)(Po + o1);
    float l = Pl[ub * 128 + row] + Pl[(ub + 1) * 128 + row];
    float inv = 1.0f / l;

    size_t gr = (size_t)(b * TT + qt * 128 + row);
    *(uint32_t*)(ATB + gr * DD + hh * HS + cp * 2) =
        packh(__float2half_rn((a.x + c.x) * inv), __float2half_rn((a.y + c.y) * inv));
}

// ---------------- RMSNorm -> fp16 ---------------------------------------------
__global__ void __launch_bounds__(256) rmsnorm_h(
    const float* __restrict__ x, const float* __restrict__ gw,
    __half* __restrict__ o)
{
    int row = blockIdx.x;
    const float* xr = x + (size_t)row * DD;
    int tid = threadIdx.x;
    float ss = 0.f;
    for (int i = tid; i < DD; i += 256) { float v = xr[i]; ss += v * v; }
    #pragma unroll
    for (int o2 = 16; o2 > 0; o2 >>= 1) ss += __shfl_xor_sync(0xffffffffu, ss, o2);
    __shared__ float red[8];
    if ((tid & 31) == 0) red[tid >> 5] = ss;
    __syncthreads();
    if (tid < 8) {
        float v = red[tid];
        #pragma unroll
        for (int o2 = 4; o2 > 0; o2 >>= 1) v += __shfl_xor_sync(0xffu, v, o2);
        if (tid == 0) red[0] = v;
    }
    __syncthreads();
    float rms = sqrtf(red[0] * (1.0f / DD));
    float inv = 1.0f / (rms + 1e-8f);
    for (int i = tid; i < DD; i += 256)
        o[(size_t)row * DD + i] = __float2half_rn(gw[i] * xr[i] * inv);
}

// ---------------- launch -----------------------------------------------------
extern "C" void kernel_launch(void* const* d_in, const int* in_sizes, int n_in,
                              void* d_out, int out_size)
{
    const float* x  = (const float*)d_in[0];
    const float* Wq = (const float*)d_in[1];
    const float* Wk = (const float*)d_in[2];
    const float* Wv = (const float*)d_in[3];
    const float* Wo = (const float*)d_in[4];
    const float* bo = (const float*)d_in[5];
    const float* W1 = (const float*)d_in[6];
    const float* b1 = (const float*)d_in[7];
    const float* W2 = (const float*)d_in[8];
    const float* b2 = (const float*)d_in[9];
    const float* g1 = (const float*)d_in[10];
    const float* g2 = (const float*)d_in[11];
    float* out = (float*)d_out;

    float *x1, *po, *pl;
    __half *ah, *qh, *atb, *h2b, *swb, *kb, *vb, *bqkv, *bo_, *b1_, *b2_;
    cudaGetSymbolAddress((void**)&x1,  g_x1);
    cudaGetSymbolAddress((void**)&po,  g_po);
    cudaGetSymbolAddress((void**)&pl,  g_pl);
    cudaGetSymbolAddress((void**)&ah,  g_ah);
    cudaGetSymbolAddress((void**)&qh,  g_qh);
    cudaGetSymbolAddress((void**)&atb, g_atb);
    cudaGetSymbolAddress((void**)&h2b, g_h2b);
    cudaGetSymbolAddress((void**)&swb, g_swb);
    cudaGetSymbolAddress((void**)&kb,  g_kb);
    cudaGetSymbolAddress((void**)&vb,  g_vb);
    cudaGetSymbolAddress((void**)&bqkv, g_bqkv);
    cudaGetSymbolAddress((void**)&bo_,  g_bo);
    cudaGetSymbolAddress((void**)&b1_,  g_b1);
    cudaGetSymbolAddress((void**)&b2_,  g_b2);

    cudaFuncSetAttribute(gemm_mma, cudaFuncAttributeMaxDynamicSharedMemorySize, GEMM_SMEM);
    cudaFuncSetAttribute(attn_tc,  cudaFuncAttributeMaxDynamicSharedMemorySize, ATT_SMEM);

    // 0) coalesced weight prep (single launch)
    prep_tr<<<PREP_GRID, 256>>>(Wq, Wk, Wv, Wo, W1, W2, bqkv, bo_, b1_, b2_);

    // 1) ah = fp16(rmsnorm(x, g1))
    rmsnorm_h<<<NT, 256>>>(x, g1, ah);

    // 2) qkv GEMM: epilogue scatters Q (scaled fp16), K, V^T per-head directly
    gemm_mma<<<dim3(QKVN / 64, NT / 128), 128, GEMM_SMEM>>>(
        ah, bqkv, nullptr, nullptr, nullptr, qh, kb, vb, NT, QKVN, DD, 2);

    // 3) attention (split-K, 24 units/bh) -> atb + partials
    attn_tc<<<dim3(24, BH), 256, ATT_SMEM>>>(qh, kb, vb, atb, po, pl);

    // 4) merge split-K partials into atb
    attn_merge<<<3072, 256>>>(po, pl, atb);

    // 5) x1 = x + atb @ Wo + bo   (<- ncu sample target)
    gemm_mma<<<dim3(DD / 64, NT / 128), 128, GEMM_SMEM>>>(
        atb, bo_, bo, x, x1, nullptr, nullptr, nullptr, NT, DD, DD, 0);

    // 6) h2b = fp16(rmsnorm(x1, g2))
    rmsnorm_h<<<NT, 256>>>(x1, g2, h2b);

    // 7) swb = swiglu(h2b @ W1' + b1)  — fused epilogue, interleaved W1
    gemm_mma<<<dim3(FF / 64, NT / 128), 128, GEMM_SMEM>>>(
        h2b, b1_, b1, nullptr, nullptr, swb, nullptr, nullptr, NT, FF, DD, 1);

    // 8) out = x1 + swb @ W2 + b2
    gemm_mma<<<dim3(DD / 64, NT / 128), 128, GEMM_SMEM>>>(
        swb, b2_, b2, x1, out, nullptr, nullptr, nullptr, NT, DD, HALF, 0);
}

// round 12
// speedup vs baseline: 2.6675x; 1.0423x over previous
#include <cuda_runtime.h>
#include <cuda_fp16.h>
#include <cstdint>
#include <cstddef>

// Problem constants
#define BB 2
#define TT 2048
#define DD 768
#define HH 12
#define HS 64
#define FF 3072
#define HALF 1536
#define NT (BB*TT)       // 4096
#define QKVN 2304        // fused q|k|v output width
#define BH 24            // B*H
// 768^-0.5 * log2(e)  (Q pre-scale so scores feed ex2 directly)
#define SCL2 0.05205878339613894f

// ---------------- scratch (device globals) -----------------------------------
__device__ float g_x1 [(size_t)NT*DD];
__device__ __half g_ah [(size_t)NT*DD];    // rmsnorm1 out
__device__ __half g_qh [(size_t)NT*DD];    // Q (pre-scaled), from QKV epilogue
__device__ __half g_atb[(size_t)NT*DD];    // attention out
__device__ __half g_h2b[(size_t)NT*DD];    // rmsnorm2 out
__device__ __half g_swb[(size_t)NT*HALF];  // swiglu out (from W1 epi)
__device__ __half g_kb [(size_t)BH*TT*HS]; // K [bh][t][64]
__device__ __half g_vb [(size_t)BH*TT*HS]; // V^T [bh][hs][T]
// split-K attention partials: [qt-4][bh][part(4)][128][64]
__device__ float g_po [(size_t)12*24*4*128*64];
__device__ float g_pl [(size_t)12*24*4*128];
// fp16 weights, layout [N][K]
__device__ __half g_bqkv[(size_t)QKVN*DD];
__device__ __half g_bo  [(size_t)DD*DD];
__device__ __half g_b1  [(size_t)FF*DD];   // column-interleaved (val,gate)
__device__ __half g_b2  [(size_t)DD*HALF];

// ---------------- helpers ----------------------------------------------------
__device__ __forceinline__ uint32_t smem_u32(const void* p) {
    uint32_t a;
    asm("{ .reg .u64 t; cvta.to.shared.u64 t, %1; cvt.u32.u64 %0, t; }" : "=r"(a) : "l"(p));
    return a;
}
__device__ __forceinline__ float ex2f(float x) {
    float r; asm("ex2.approx.ftz.f32 %0, %1;" : "=f"(r) : "f"(x)); return r;
}
#define CPASYNC(d, s) asm volatile("cp.async.cg.shared.global [%0], [%1], 16;" :: "r"(d), "l"(s) : "memory")
#define CPCOMMIT()    asm volatile("cp.async.commit_group;" ::: "memory")
#define CPWAIT(n)     asm volatile("cp.async.wait_group %0;" :: "n"(n) : "memory")
#define LDSM4(r, a)                                                              \
    asm volatile("ldmatrix.sync.aligned.m8n8.x4.shared.b16 {%0,%1,%2,%3}, [%4];" \
        : "=r"((r)[0]), "=r"((r)[1]), "=r"((r)[2]), "=r"((r)[3]) : "r"(a))
#define MMA16816(c, a, b0, b1)                                                   \
    asm volatile("mma.sync.aligned.m16n8k16.row.col.f32.f16.f16.f32 "            \
        "{%0,%1,%2,%3}, {%4,%5,%6,%7}, {%8,%9}, {%0,%1,%2,%3};"                  \
        : "+f"((c)[0]), "+f"((c)[1]), "+f"((c)[2]), "+f"((c)[3])                 \
        : "r"((a)[0]), "r"((a)[1]), "r"((a)[2]), "r"((a)[3]), "r"(b0), "r"(b1))

__device__ __forceinline__ uint32_t packh(__half a, __half b) {
    return (uint32_t)__half_as_ushort(a) | ((uint32_t)__half_as_ushort(b) << 16);
}

// ---------------- coalesced weight prep: smem tile transpose -------------------
__global__ void __launch_bounds__(256) prep_tr(
    const float* __restrict__ Wq, const float* __restrict__ Wk,
    const float* __restrict__ Wv, const float* __restrict__ Wo,
    const float* __restrict__ W1, const float* __restrict__ W2,
    __half* __restrict__ bqkv, __half* __restrict__ bo,
    __half* __restrict__ b1,  __half* __restrict__ b2)
{
    __shared__ float ts[32][33];
    int bid = blockIdx.x;
    int tx = threadIdx.x & 31, ty = threadIdx.x >> 5;

    const float* W; __half* dst;
    int K, mode, srcLd, tn, tk;
    if (bid < 2304) {
        int m = bid / 576, lt = bid - m * 576;
        W = (m == 0) ? Wq : (m == 1) ? Wk : (m == 2) ? Wv : Wo;
        dst = (m < 3) ? bqkv + (size_t)m * 768 * 768 : bo;
        K = 768; mode = (m < 3) ? 1 : 0; srcLd = 768;
        tn = lt / 24; tk = lt - (lt / 24) * 24;
    } else if (bid < 4608) {
        int lt = bid - 2304;
        W = W1; dst = b1; K = 768; mode = 2; srcLd = 3072;
        tn = lt / 24; tk = lt - (lt / 24) * 24;
    } else {
        int lt = bid - 4608;
        W = W2; dst = b2; K = 1536; mode = 0; srcLd = 768;
        tn = lt / 48; tk = lt - (lt / 48) * 48;
    }
    int k0 = tk * 32, n0 = tn * 32;

    #pragma unroll
    for (int i = 0; i < 4; i++) {
        int kk = ty + i * 8;
        float v; int col;
        if (mode == 0) {
            v = W[(size_t)(k0 + kk) * srcLd + n0 + tx];
            col = tx;
        } else if (mode == 1) {
            v = W[(size_t)(n0 >> 6) * (768 * 64) + (size_t)(k0 + kk) * 64 + (n0 & 63) + tx];
            col = tx;
        } else {
            int j = tx & 15, grp = tx >> 4;
            v = W[(size_t)(k0 + kk) * 3072 + (grp ? HALF : 0) + (n0 >> 1) + j];
            col = 2 * j + grp;
        }
        ts[kk][col] = v;
    }
    __syncthreads();
    #pragma unroll
    for (int i = 0; i < 4; i++) {
        int nn = ty + i * 8;
        dst[(size_t)(n0 + nn) * K + k0 + tx] = __float2half_rn(ts[tx][nn]);
    }
}
#define PREP_GRID 5760

// ---------------- mma.sync fp16 GEMM ------------------------------------------
// CTA 128x64, 128 threads (2x2 warps, warp tile 64x32), K-block 64, 4 CTAs/SM.
#define KB 64
#define PADE 72
#define ATILE (128*PADE*2)       // 18432
#define BTILE (64*PADE*2)        // 9216
#define STGB  (ATILE+BTILE)      // 27648
#define GEMM_SMEM (2*STGB)       // 55296

__global__ void __launch_bounds__(128, 4) gemm_mma(
    const __half* __restrict__ Ap, const __half* __restrict__ Bp,
    const float* __restrict__ bias, const float* __restrict__ resid,
    float* __restrict__ C, __half* __restrict__ Csp,
    __half* __restrict__ Kout, __half* __restrict__ Vout,
    int M, int N, int K, int emode)
{
    extern __shared__ char sm[];
    int tid = threadIdx.x, lane = tid & 31, wid = tid >> 5;
    int wm = wid >> 1, wn = wid & 1;
    int bm = blockIdx.y * 128, bn = blockIdx.x * 64;
    uint32_t sbase = smem_u32(sm);

    float acc[4][4][4];
    #pragma unroll
    for (int i = 0; i < 4; i++)
        #pragma unroll
        for (int j = 0; j < 4; j++)
            #pragma unroll
            for (int q = 0; q < 4; q++) acc[i][j][q] = 0.f;

    int a_r = lane & 15, a_c = (lane & 16) ? 8 : 0;
    int b_r = ((lane >> 4) << 3) + (lane & 7), b_c = (lane & 8);
    const int KBn = K / KB;

    auto load_stage = [&](int kb, int stg) {
        #pragma unroll
        for (int i = 0; i < 12; i++) {
            int c = i * 128 + tid;
            int row = c >> 3, cc = c & 7;
            uint32_t dst;
            const __half* src;
            if (i < 8) {
                dst = sbase + stg * STGB + (uint32_t)(row * (PADE * 2) + cc * 16);
                src = Ap + (size_t)(bm + row) * K + kb * KB + cc * 8;
            } else {
                int r2 = row - 128;
                dst = sbase + stg * STGB + ATILE + (uint32_t)(r2 * (PADE * 2) + cc * 16);
                src = Bp + (size_t)(bn + r2) * K + kb * KB + cc * 8;
            }
            CPASYNC(dst, src);
        }
    };

    load_stage(0, 0);
    CPCOMMIT();

    for (int kb = 0; kb < KBn; kb++) {
        CPWAIT(0);
        __syncthreads();
        if (kb + 1 < KBn) { load_stage(kb + 1, (kb + 1) & 1); CPCOMMIT(); }

        uint32_t sa = sbase + (kb & 1) * STGB;
        uint32_t aof = sa, bof = sa + ATILE;
        #pragma unroll
        for (int ks = 0; ks < KB; ks += 16) {
            uint32_t af[4][4], bf2[2][4];
            #pragma unroll
            for (int mt = 0; mt < 4; mt++) {
                uint32_t off = (uint32_t)(((wm * 64 + mt * 16 + a_r) * PADE + ks + a_c) * 2);
                LDSM4(af[mt], aof + off);
            }
            #pragma unroll
            for (int np = 0; np < 2; np++) {
                uint32_t off = (uint32_t)(((wn * 32 + np * 16 + b_r) * PADE + ks + b_c) * 2);
                LDSM4(bf2[np], bof + off);
            }
            #pragma unroll
            for (int mt = 0; mt < 4; mt++)
                #pragma unroll
                for (int nt = 0; nt < 4; nt++)
                    MMA16816(acc[mt][nt], af[mt],
                             bf2[nt >> 1][(nt & 1) * 2], bf2[nt >> 1][(nt & 1) * 2 + 1]);
        }
    }

    int g = lane >> 2, t = lane & 3;
    if (emode == 0) {
        #pragma unroll
        for (int mt = 0; mt < 4; mt++) {
            #pragma unroll
            for (int half = 0; half < 2; half++) {
                int row = bm + wm * 64 + mt * 16 + g + half * 8;
                float* cp = C + (size_t)row * N;
                const float* rp = resid ? (resid + (size_t)row * N) : nullptr;
                #pragma unroll
                for (int nt = 0; nt < 4; nt++) {
                    int col = bn + wn * 32 + nt * 8 + t * 2;
                    float2 v;
                    v.x = acc[mt][nt][half * 2 + 0];
                    v.y = acc[mt][nt][half * 2 + 1];
                    if (bias) {
                        float2 b2v = *(const float2*)(bias + col);
                        v.x += b2v.x; v.y += b2v.y;
                    }
                    if (rp) {
                        float2 r2v = *(const float2*)(rp + col);
                        v.x += r2v.x; v.y += r2v.y;
                    }
                    *(float2*)(cp + col) = v;
                }
            }
        }
    } else if (emode == 1) {
        #pragma unroll
        for (int mt = 0; mt < 4; mt++) {
            #pragma unroll
            for (int half = 0; half < 2; half++) {
                int row = bm + wm * 64 + mt * 16 + g + half * 8;
                #pragma unroll
                for (int nt = 0; nt < 4; nt++) {
                    int gcol = bn + wn * 32 + nt * 8 + t * 2;
                    int j = gcol >> 1;
                    float val = acc[mt][nt][half * 2 + 0] + bias[j];
                    float gt  = acc[mt][nt][half * 2 + 1] + bias[HALF + j];
                    float s = gt / (1.0f + __expf(-gt));
                    Csp[(size_t)row * HALF + j] = __float2half_rn(s * val);
                }
            }
        }
    } else {
        #pragma unroll
        for (int mt = 0; mt < 4; mt++) {
            #pragma unroll
            for (int half = 0; half < 2; half++) {
                int row = bm + wm * 64 + mt * 16 + g + half * 8;
                int bq = row >> 11, t2 = row & (TT - 1);
                #pragma unroll
                for (int nt = 0; nt < 4; nt++) {
                    int col = bn + wn * 32 + nt * 8 + t * 2;
                    float vx = acc[mt][nt][half * 2 + 0];
                    float vy = acc[mt][nt][half * 2 + 1];
                    if (col < DD) {
                        *(uint32_t*)(Csp + (size_t)row * DD + col) =
                            packh(__float2half_rn(vx * SCL2), __float2half_rn(vy * SCL2));
                    } else if (col < 2 * DD) {
                        int c = col - DD; int h2 = c >> 6, hs = c & 63;
                        *(uint32_t*)(Kout + (((size_t)(bq * HH + h2) * TT + t2) << 6) + hs) =
                            packh(__float2half_rn(vx), __float2half_rn(vy));
                    } else {
                        int c = col - 2 * DD; int h2 = c >> 6, hs = c & 63;
                        size_t a0 = ((size_t)(bq * HH + h2) * 64 + hs) * TT + t2;
                        Vout[a0]      = __float2half_rn(vx);
                        Vout[a0 + TT] = __float2half_rn(vy);
                    }
                }
            }
        }
    }
}

// ---------------- tensor-core causal flash attention (fp16, fine split-K) -----
// 40 units per bh (tile spans <= 8), longest-first via blockIdx.y ordering.
// qt<=3 unsplit -> direct output; qt>=4 parts -> fp32 partials, additive merge.
#define ATT_STG 18432
#define ATT_SMEM (18432 + 3*ATT_STG)   // 73728

__global__ void __launch_bounds__(256, 2) attn_tc(
    const __half* __restrict__ Qb, const __half* __restrict__ KBi,
    const __half* __restrict__ VBi, __half* __restrict__ ATB,
    float* __restrict__ Po, float* __restrict__ Pl)
{
    static const signed char UQT[40] = {15,15,15,15,14,14,11,11,11,10,7,7,3,
                                        14,14,13,13,13,13,12,12,10,10,9,9,6,6,
                                        12,12,9,8,8,8,5,5,2,4,4,1,0};
    static const signed char UPP[40] = {0,1,2,3,0,1,0,1,2,0,0,1,0,
                                        2,3,0,1,2,3,0,1,1,2,0,1,0,1,
                                        2,3,2,0,1,2,0,1,0,0,1,0,0};
    static const signed char UST[40] = {0,8,16,24,0,8,0,8,16,0,0,8,0,
                                        16,23,0,7,14,21,0,7,8,15,0,7,0,7,
                                        14,20,14,0,6,12,0,6,0,0,5,0,0};
    static const signed char ULN[40] = {8,8,8,8,8,8,8,8,8,8,8,8,8,
                                        7,7,7,7,7,7,7,7,7,7,7,7,7,7,
                                        6,6,6,6,6,6,6,6,6,5,5,4,2};
    extern __shared__ char sm[];
    uint32_t sbase = smem_u32(sm);
    int tid = threadIdx.x, lane = tid & 31, wid = tid >> 5;
    int bh = blockIdx.x, u = blockIdx.y;
    int qt = UQT[u], part = UPP[u];
    int kt0 = UST[u], nloc = ULN[u];
    int b = bh / HH, hh = bh % HH;
    int q0 = qt * 128;

    int a_r = lane & 15, a_c = (lane & 16) ? 8 : 0;
    int b_r = ((lane >> 4) << 3) + (lane & 7), b_c = lane & 8;
    int g = lane >> 2, tq = lane & 3;
    const uint32_t ONES = 0x3C003C00u;

    auto ldkv = [&](int kt, int stg) {
        uint32_t sb2 = sbase + 18432 + stg * ATT_STG;
        size_t kbase = ((size_t)bh * TT + kt * 64) * HS;
        size_t vbase = (size_t)bh * HS * TT + kt * 64;
        #pragma unroll
        for (int i = 0; i < 4; i++) {
            int ch = i * 256 + tid;
            int tile = ch >> 9;
            int r = (ch >> 3) & 63, cc = ch & 7;
            uint32_t dst = sb2 + tile * 9216 + r * 144 + cc * 16;
            const __half* src = (tile == 0)
                ? KBi + kbase + r * 64 + cc * 8
                : VBi + vbase + (size_t)r * TT + cc * 8;
            CPASYNC(dst, src);
        }
    };

    #pragma unroll
    for (int i = 0; i < 4; i++) {
        int p = i * 256 + tid;
        int row = p >> 3, cc = p & 7;
        CPASYNC(sbase + (uint32_t)(row * 144 + cc * 16),
                Qb + (size_t)(b * TT + q0 + row) * DD + hh * HS + cc * 8);
    }
    CPCOMMIT();
    ldkv(kt0, 0);     CPCOMMIT();
    ldkv(kt0 + 1, 1); CPCOMMIT();

    float oacc[8][4];
    #pragma unroll
    for (int n = 0; n < 8; n++)
        #pragma unroll
        for (int j = 0; j < 4; j++) oacc[n][j] = 0.f;
    float lacc[4] = {0.f, 0.f, 0.f, 0.f};

    for (int it = 0; it < nloc; it++) {
        if (it + 1 < nloc) { CPWAIT(1); } else { CPWAIT(0); }
        __syncthreads();
        if (it + 2 < nloc) { ldkv(kt0 + it + 2, (it + 2) % 3); CPCOMMIT(); }

        int kt = kt0 + it;
        uint32_t KHb = sbase + 18432 + (it % 3) * ATT_STG;
        uint32_t VHb = KHb + 9216;

        float sacc[8][4];
        #pragma unroll
        for (int n = 0; n < 8; n++)
            #pragma unroll
            for (int j = 0; j < 4; j++) sacc[n][j] = 0.f;

        #pragma unroll
        for (int ks = 0; ks < 4; ks++) {
            uint32_t qh[4];
            uint32_t qa = sbase + (uint32_t)(((wid * 16 + a_r) * 72 + ks * 16 + a_c) * 2);
            LDSM4(qh, qa);
            #pragma unroll
            for (int nt2 = 0; nt2 < 4; nt2++) {
                uint32_t kf[4];
                uint32_t ka = (uint32_t)(((nt2 * 16 + b_r) * 72 + ks * 16 + b_c) * 2);
                LDSM4(kf, KHb + ka);
                MMA16816(sacc[2*nt2],     qh, kf[0], kf[1]);
                MMA16816(sacc[2*nt2 + 1], qh, kf[2], kf[3]);
            }
        }

        if (kt >= 2 * qt) {        // diagonal tiles only
            int r0 = q0 + wid * 16 + g, r1 = r0 + 8;
            int cb = kt * 64 + tq * 2;
            #pragma unroll
            for (int n = 0; n < 8; n++) {
                #pragma unroll
                for (int j = 0; j < 4; j++) {
                    int c = cb + n * 8 + (j & 1);
                    int r = (j < 2) ? r0 : r1;
                    sacc[n][j] = (c <= r) ? ex2f(sacc[n][j]) : 0.f;
                }
            }
        } else {
            #pragma unroll
            for (int n = 0; n < 8; n++)
                #pragma unroll
                for (int j = 0; j < 4; j++)
                    sacc[n][j] = ex2f(sacc[n][j]);
        }

        #pragma unroll
        for (int pk = 0; pk < 4; pk++) {
            uint32_t pa[4];
            pa[0] = packh(__float2half_rn(sacc[2*pk][0]),   __float2half_rn(sacc[2*pk][1]));
            pa[1] = packh(__float2half_rn(sacc[2*pk][2]),   __float2half_rn(sacc[2*pk][3]));
            pa[2] = packh(__float2half_rn(sacc[2*pk+1][0]), __float2half_rn(sacc[2*pk+1][1]));
            pa[3] = packh(__float2half_rn(sacc[2*pk+1][2]), __float2half_rn(sacc[2*pk+1][3]));
            MMA16816(lacc, pa, ONES, ONES);
            #pragma unroll
            for (int nt2 = 0; nt2 < 4; nt2++) {
                uint32_t vf[4];
                uint32_t va = (uint32_t)(((nt2 * 16 + b_r) * 72 + pk * 16 + b_c) * 2);
                LDSM4(vf, VHb + va);
                MMA16816(oacc[2*nt2],     pa, vf[0], vf[1]);
                MMA16816(oacc[2*nt2 + 1], pa, vf[2], vf[3]);
            }
        }
    }

    if (qt <= 3) {
        // unsplit: normalize and write fp16 output directly
        float inv0 = 1.0f / lacc[0], inv1 = 1.0f / lacc[2];
        size_t rg0 = (size_t)(b * TT + q0 + wid * 16 + g);
        size_t rg1 = rg0 + 8;
        int lc = hh * HS + tq * 2;
        #pragma unroll
        for (int n = 0; n < 8; n++) {
            *(uint32_t*)(ATB + rg0 * DD + lc + n * 8) =
                packh(__float2half_rn(oacc[n][0] * inv0), __float2half_rn(oacc[n][1] * inv0));
            *(uint32_t*)(ATB + rg1 * DD + lc + n * 8) =
                packh(__float2half_rn(oacc[n][2] * inv1), __float2half_rn(oacc[n][3] * inv1));
        }
    } else {
        // split part: write raw fp32 partials at [qt-4][bh][part]
        int slot = ((qt - 4) * 24 + bh) * 4 + part;
        int r0 = wid * 16 + g;
        float* p0 = Po + ((size_t)slot * 128 + r0) * 64 + tq * 2;
        float* p1 = Po + ((size_t)slot * 128 + r0 + 8) * 64 + tq * 2;
        #pragma unroll
        for (int n = 0; n < 8; n++) {
            float2 v0; v0.x = oacc[n][0]; v0.y = oacc[n][1];
            float2 v1; v1.x = oacc[n][2]; v1.y = oacc[n][3];
            *(float2*)(p0 + n * 8) = v0;
            *(float2*)(p1 + n * 8) = v1;
        }
        if (tq == 0) {
            Pl[(size_t)slot * 128 + r0]     = lacc[0];
            Pl[(size_t)slot * 128 + r0 + 8] = lacc[2];
        }
    }
}

// ---------------- merge split-K attention partials -----------------------------
// qt 4..15: sum np = ceil((2qt+2)/8) parts. 12 x 24 x 128 x 32 threads.
__global__ void __launch_bounds__(256) attn_merge(
    const float* __restrict__ Po, const float* __restrict__ Pl,
    __half* __restrict__ ATB)
{
    int idx = blockIdx.x * 256 + threadIdx.x;
    int cp = idx & 31;
    int t  = idx >> 5;
    int row = t & 127;
    int t2 = t >> 7;
    int bh = t2 % 24, qi = t2 / 24;
    int qt = qi + 4;
    int np = (2 * qt + 2 + 7) >> 3;
    int b = bh / HH, hh = bh % HH;

    size_t slot0 = (size_t)(qi * 24 + bh) * 4;
    float ox = 0.f, oy = 0.f, l = 0.f;
    for (int p = 0; p < np; p++) {
        size_t sp = slot0 + p;
        float2 v = *(const float2*)(Po + (sp * 128 + row) * 64 + cp * 2);
        ox += v.x; oy += v.y;
        l += Pl[sp * 128 + row];
    }
    float inv = 1.0f / l;

    size_t gr = (size_t)(b * TT + qt * 128 + row);
    *(uint32_t*)(ATB + gr * DD + hh * HS + cp * 2) =
        packh(__float2half_rn(ox * inv), __float2half_rn(oy * inv));
}

// ---------------- RMSNorm -> fp16 ---------------------------------------------
__global__ void __launch_bounds__(256) rmsnorm_h(
    const float* __restrict__ x, const float* __restrict__ gw,
    __half* __restrict__ o)
{
    int row = blockIdx.x;
    const float* xr = x + (size_t)row * DD;
    int tid = threadIdx.x;
    float ss = 0.f;
    for (int i = tid; i < DD; i += 256) { float v = xr[i]; ss += v * v; }
    #pragma unroll
    for (int o2 = 16; o2 > 0; o2 >>= 1) ss += __shfl_xor_sync(0xffffffffu, ss, o2);
    __shared__ float red[8];
    if ((tid & 31) == 0) red[tid >> 5] = ss;
    __syncthreads();
    if (tid < 8) {
        float v = red[tid];
        #pragma unroll
        for (int o2 = 4; o2 > 0; o2 >>= 1) v += __shfl_xor_sync(0xffu, v, o2);
        if (tid == 0) red[0] = v;
    }
    __syncthreads();
    float rms = sqrtf(red[0] * (1.0f / DD));
    float inv = 1.0f / (rms + 1e-8f);
    for (int i = tid; i < DD; i += 256)
        o[(size_t)row * DD + i] = __float2half_rn(gw[i] * xr[i] * inv);
}

// ---------------- launch -----------------------------------------------------
extern "C" void kernel_launch(void* const* d_in, const int* in_sizes, int n_in,
                              void* d_out, int out_size)
{
    const float* x  = (const float*)d_in[0];
    const float* Wq = (const float*)d_in[1];
    const float* Wk = (const float*)d_in[2];
    const float* Wv = (const float*)d_in[3];
    const float* Wo = (const float*)d_in[4];
    const float* bo = (const float*)d_in[5];
    const float* W1 = (const float*)d_in[6];
    const float* b1 = (const float*)d_in[7];
    const float* W2 = (const float*)d_in[8];
    const float* b2 = (const float*)d_in[9];
    const float* g1 = (const float*)d_in[10];
    const float* g2 = (const float*)d_in[11];
    float* out = (float*)d_out;

    float *x1, *po, *pl;
    __half *ah, *qh, *atb, *h2b, *swb, *kb, *vb, *bqkv, *bo_, *b1_, *b2_;
    cudaGetSymbolAddress((void**)&x1,  g_x1);
    cudaGetSymbolAddress((void**)&po,  g_po);
    cudaGetSymbolAddress((void**)&pl,  g_pl);
    cudaGetSymbolAddress((void**)&ah,  g_ah);
    cudaGetSymbolAddress((void**)&qh,  g_qh);
    cudaGetSymbolAddress((void**)&atb, g_atb);
    cudaGetSymbolAddress((void**)&h2b, g_h2b);
    cudaGetSymbolAddress((void**)&swb, g_swb);
    cudaGetSymbolAddress((void**)&kb,  g_kb);
    cudaGetSymbolAddress((void**)&vb,  g_vb);
    cudaGetSymbolAddress((void**)&bqkv, g_bqkv);
    cudaGetSymbolAddress((void**)&bo_,  g_bo);
    cudaGetSymbolAddress((void**)&b1_,  g_b1);
    cudaGetSymbolAddress((void**)&b2_,  g_b2);

    cudaFuncSetAttribute(gemm_mma, cudaFuncAttributeMaxDynamicSharedMemorySize, GEMM_SMEM);
    cudaFuncSetAttribute(attn_tc,  cudaFuncAttributeMaxDynamicSharedMemorySize, ATT_SMEM);

    // 0) coalesced weight prep (single launch)
    prep_tr<<<PREP_GRID, 256>>>(Wq, Wk, Wv, Wo, W1, W2, bqkv, bo_, b1_, b2_);

    // 1) ah = fp16(rmsnorm(x, g1))
    rmsnorm_h<<<NT, 256>>>(x, g1, ah);

    // 2) qkv GEMM: epilogue scatters Q (scaled by SCL*log2e), K, V^T per-head
    gemm_mma<<<dim3(QKVN / 64, NT / 128), 128, GEMM_SMEM>>>(
        ah, bqkv, nullptr, nullptr, nullptr, qh, kb, vb, NT, QKVN, DD, 2);

    // 3) attention (fine split-K, 40 units/bh, longest-first)
    attn_tc<<<dim3(BH, 40), 256, ATT_SMEM>>>(qh, kb, vb, atb, po, pl);

    // 4) merge split-K partials into atb (qt 4..15)
    attn_merge<<<4608, 256>>>(po, pl, atb);

    // 5) x1 = x + atb @ Wo + bo   (<- ncu sample target)
    gemm_mma<<<dim3(DD / 64, NT / 128), 128, GEMM_SMEM>>>(
        atb, bo_, bo, x, x1, nullptr, nullptr, nullptr, NT, DD, DD, 0);

    // 6) h2b = fp16(rmsnorm(x1, g2))
    rmsnorm_h<<<NT, 256>>>(x1, g2, h2b);

    // 7) swb = swiglu(h2b @ W1' + b1)  — fused epilogue, interleaved W1
    gemm_mma<<<dim3(FF / 64, NT / 128), 128, GEMM_SMEM>>>(
        h2b, b1_, b1, nullptr, nullptr, swb, nullptr, nullptr, NT, FF, DD, 1);

    // 8) out = x1 + swb @ W2 + b2
    gemm_mma<<<dim3(DD / 64, NT / 128), 128, GEMM_SMEM>>>(
        swb, b2_, b2, x1, out, nullptr, nullptr, nullptr, NT, DD, HALF, 0);
}